// round 2
// baseline (speedup 1.0000x reference)
#include <cuda_runtime.h>
#include <cuda_bf16.h>
#include <math.h>

// Problem constants
#define S 4096
#define D 256
#define HEADS 8
#define DH 32
#define FF 1024
#define NLAYERS 4
#define HALF_WIN 256
#define EPS 1e-5f

// ---------------- scratch (device globals, no allocation allowed) ----------------
__device__ float g_n [S * D];
__device__ float g_q [S * D];
__device__ float g_k [S * D];
__device__ float g_v [S * D];
__device__ float g_o [S * D];
__device__ float g_ff[S * FF];

// ---------------- helpers ----------------
__device__ __forceinline__ float gelu_tanh(float x) {
    // JAX default gelu (approximate=True)
    const float c = 0.7978845608028654f; // sqrt(2/pi)
    float x3 = x * x * x;
    float t = tanhf(c * (x + 0.044715f * x3));
    return 0.5f * x * (1.0f + t);
}

// ---------------- copy ----------------
__global__ void copy_kernel(const float* __restrict__ in, float* __restrict__ out, int n) {
    int i = blockIdx.x * blockDim.x + threadIdx.x;
    if (i < n) out[i] = in[i];
}

// ---------------- LayerNorm (no affine), one block per row of D=256 ----------------
__global__ void ln_kernel(const float* __restrict__ in, float* __restrict__ out) {
    __shared__ float s1[D];
    __shared__ float s2[D];
    int row = blockIdx.x;
    int tid = threadIdx.x;
    float v = in[row * D + tid];
    s1[tid] = v;
    s2[tid] = v * v;
    __syncthreads();
    for (int off = D / 2; off > 0; off >>= 1) {
        if (tid < off) {
            s1[tid] += s1[tid + off];
            s2[tid] += s2[tid + off];
        }
        __syncthreads();
    }
    float mean = s1[0] * (1.0f / D);
    float var  = s2[0] * (1.0f / D) - mean * mean;
    float rstd = rsqrtf(var + EPS);
    out[row * D + tid] = (v - mean) * rstd;
}

// ---------------- Tiled GEMM: C[M,N] = A[M,K] @ W[K,N] + bias (+gelu) (+res) ----------------
#define BM 64
#define BN 64
#define BK 16

__global__ void gemm_kernel(const float* __restrict__ A, const float* __restrict__ W,
                            const float* __restrict__ bias, const float* __restrict__ res,
                            float* __restrict__ C, int M, int N, int K, int act) {
    __shared__ float As[BK][BM];
    __shared__ float Ws[BK][BN];

    int tx = threadIdx.x;       // 0..15
    int ty = threadIdx.y;       // 0..15
    int tid = ty * 16 + tx;     // 0..255
    int row0 = blockIdx.y * BM;
    int col0 = blockIdx.x * BN;

    float acc[4][4];
#pragma unroll
    for (int i = 0; i < 4; i++)
#pragma unroll
        for (int j = 0; j < 4; j++) acc[i][j] = 0.0f;

    int ar = tid >> 2;            // 0..63
    int ac = (tid & 3) << 2;      // 0,4,8,12
    int wr = tid >> 4;            // 0..15
    int wc = (tid & 15) << 2;     // 0..60

    for (int k0 = 0; k0 < K; k0 += BK) {
        float4 a = *(const float4*)&A[(row0 + ar) * K + k0 + ac];
        As[ac + 0][ar] = a.x;
        As[ac + 1][ar] = a.y;
        As[ac + 2][ar] = a.z;
        As[ac + 3][ar] = a.w;
        *(float4*)&Ws[wr][wc] = *(const float4*)&W[(k0 + wr) * N + col0 + wc];
        __syncthreads();

#pragma unroll
        for (int kk = 0; kk < BK; kk++) {
            float4 a4 = *(float4*)&As[kk][ty * 4];
            float4 b4 = *(float4*)&Ws[kk][tx * 4];
            float av[4] = {a4.x, a4.y, a4.z, a4.w};
            float bv[4] = {b4.x, b4.y, b4.z, b4.w};
#pragma unroll
            for (int i = 0; i < 4; i++)
#pragma unroll
                for (int j = 0; j < 4; j++)
                    acc[i][j] = fmaf(av[i], bv[j], acc[i][j]);
        }
        __syncthreads();
    }

#pragma unroll
    for (int i = 0; i < 4; i++) {
        int r = row0 + ty * 4 + i;
#pragma unroll
        for (int j = 0; j < 4; j++) {
            int c = col0 + tx * 4 + j;
            float val = acc[i][j] + bias[c];
            if (act) val = gelu_tanh(val);
            if (res) val += res[r * N + c];
            C[r * N + c] = val;
        }
    }
}

// ---------------- Sliding-window attention ----------------
// One block per query (8 warps = 8 heads, 256 threads).
// Per warp: q for its head held in 32 registers per lane, keys processed in
// chunks of 32 with lane <-> key inside the score step, lane <-> dim in the
// PV accumulation (broadcast p via shuffle, coalesced v row loads).
__global__ void attn_kernel(const float* __restrict__ q, const float* __restrict__ k,
                            const float* __restrict__ v, float* __restrict__ o) {
    __shared__ float qs[D];
    int i = blockIdx.x;                 // query index
    int tid = threadIdx.x;
    int head = tid >> 5;                // 0..7
    int lane = tid & 31;
    const float scale = 0.17677669529663687f; // 1/sqrt(32)

    qs[tid] = q[i * D + tid] * scale;
    __syncthreads();

    // preload this head's q into registers (same 32 values in all lanes)
    float qr[DH];
#pragma unroll
    for (int d = 0; d < DH; d++) qr[d] = qs[head * DH + d];

    int j0 = max(0, i - HALF_WIN);
    int j1 = min(S - 1, i + HALF_WIN);

    float m = -1e30f, l = 0.0f, acc = 0.0f;

    for (int jc = j0; jc <= j1; jc += 32) {
        int j = jc + lane;
        float s = -1e30f;
        if (j <= j1) {
            const float* krow = k + (size_t)j * D + head * DH;
            float dot = 0.0f;
#pragma unroll
            for (int d = 0; d < DH; d += 4) {
                float4 k4 = *(const float4*)&krow[d];
                dot = fmaf(k4.x, qr[d + 0], dot);
                dot = fmaf(k4.y, qr[d + 1], dot);
                dot = fmaf(k4.z, qr[d + 2], dot);
                dot = fmaf(k4.w, qr[d + 3], dot);
            }
            s = dot;
        }
        // chunk max
        float cm = s;
#pragma unroll
        for (int off = 16; off > 0; off >>= 1)
            cm = fmaxf(cm, __shfl_xor_sync(0xffffffffu, cm, off));
        float mn = fmaxf(m, cm);
        float corr = __expf(m - mn);
        float p = (j <= j1) ? __expf(s - mn) : 0.0f;
        // sum of p over chunk
        float ps = p;
#pragma unroll
        for (int off = 16; off > 0; off >>= 1)
            ps += __shfl_xor_sync(0xffffffffu, ps, off);
        l = l * corr + ps;
        acc *= corr;
        m = mn;
        // PV: lane <-> dim, broadcast p[jj]
        int nvalid = min(32, j1 - jc + 1);
        const float* vbase = v + (size_t)jc * D + head * DH + lane;
        for (int jj = 0; jj < nvalid; jj++) {
            float pj = __shfl_sync(0xffffffffu, p, jj);
            acc = fmaf(pj, vbase[(size_t)jj * D], acc);
        }
    }
    o[i * D + head * DH + lane] = acc / l;
}

// ---------------- launch ----------------
extern "C" void kernel_launch(void* const* d_in, const int* in_sizes, int n_in,
                              void* d_out, int out_size) {
    const float* x  = (const float*)d_in[0];
    const float* wq = (const float*)d_in[1];
    const float* bq = (const float*)d_in[2];
    const float* wk = (const float*)d_in[3];
    const float* bk = (const float*)d_in[4];
    const float* wv = (const float*)d_in[5];
    const float* bv = (const float*)d_in[6];
    const float* wo = (const float*)d_in[7];
    const float* bo = (const float*)d_in[8];
    const float* w1 = (const float*)d_in[9];
    const float* b1 = (const float*)d_in[10];
    const float* w2 = (const float*)d_in[11];
    const float* b2 = (const float*)d_in[12];

    float* h = (float*)d_out;   // residual stream lives in the output buffer

    float *n, *q, *k, *v, *o, *ff;
    cudaGetSymbolAddress((void**)&n,  g_n);
    cudaGetSymbolAddress((void**)&q,  g_q);
    cudaGetSymbolAddress((void**)&k,  g_k);
    cudaGetSymbolAddress((void**)&v,  g_v);
    cudaGetSymbolAddress((void**)&o,  g_o);
    cudaGetSymbolAddress((void**)&ff, g_ff);

    // h = x
    copy_kernel<<<(S * D + 255) / 256, 256>>>(x, h, S * D);

    dim3 tb(16, 16);
    dim3 grid_d(D / BN, S / BM);    // N=256
    dim3 grid_f(FF / BN, S / BM);   // N=1024

    for (int l = 0; l < NLAYERS; l++) {
        const float* lwq = wq + (size_t)l * D * D;
        const float* lwk = wk + (size_t)l * D * D;
        const float* lwv = wv + (size_t)l * D * D;
        const float* lwo = wo + (size_t)l * D * D;
        const float* lw1 = w1 + (size_t)l * D * FF;
        const float* lw2 = w2 + (size_t)l * FF * D;
        const float* lbq = bq + (size_t)l * D;
        const float* lbk = bk + (size_t)l * D;
        const float* lbv = bv + (size_t)l * D;
        const float* lbo = bo + (size_t)l * D;
        const float* lb1 = b1 + (size_t)l * FF;
        const float* lb2 = b2 + (size_t)l * D;

        // n = LN(h)
        ln_kernel<<<S, D>>>(h, n);
        // q,k,v = n @ W + b
        gemm_kernel<<<grid_d, tb>>>(n, lwq, lbq, nullptr, q, S, D, D, 0);
        gemm_kernel<<<grid_d, tb>>>(n, lwk, lbk, nullptr, k, S, D, D, 0);
        gemm_kernel<<<grid_d, tb>>>(n, lwv, lbv, nullptr, v, S, D, D, 0);
        // o = sliding-window attention(q,k,v)
        attn_kernel<<<S, HEADS * 32>>>(q, k, v, o);
        // h = h + o @ wo + bo
        gemm_kernel<<<grid_d, tb>>>(o, lwo, lbo, h, h, S, D, D, 0);
        // h = LN(h)   (in place)
        ln_kernel<<<S, D>>>(h, h);
        // ff = gelu(h @ w1 + b1)
        gemm_kernel<<<grid_f, tb>>>(h, lw1, lb1, nullptr, ff, S, FF, D, 1);
        // h = h + ff @ w2 + b2
        gemm_kernel<<<grid_d, tb>>>(ff, lw2, lb2, h, h, S, D, FF, 0);
    }
}

// round 4
// speedup vs baseline: 2.2540x; 2.2540x over previous
#include <cuda_runtime.h>
#include <cuda_bf16.h>
#include <math.h>

// Problem constants
#define S 4096
#define D 256
#define HEADS 8
#define DH 32
#define FF 1024
#define NLAYERS 4
#define HALF_WIN 256
#define EPS 1e-5f
#define QT 32            // queries per attention block

// ---------------- scratch (device globals, no allocation allowed) ----------------
__device__ float g_n  [S * D];
__device__ float g_qkv[3 * S * D];
__device__ float g_o  [S * D];
__device__ float g_ff [S * FF];

// ---------------- helpers ----------------
__device__ __forceinline__ float gelu_tanh(float x) {
    const float c = 0.7978845608028654f; // sqrt(2/pi)
    float x3 = x * x * x;
    float t = tanhf(c * (x + 0.044715f * x3));
    return 0.5f * x * (1.0f + t);
}

// ---------------- copy ----------------
__global__ void copy_kernel(const float* __restrict__ in, float* __restrict__ out, int n) {
    int i = blockIdx.x * blockDim.x + threadIdx.x;
    if (i < n) out[i] = in[i];
}

// ---------------- LayerNorm (no affine), one block per row of D=256 ----------------
__global__ void ln_kernel(const float* __restrict__ in, float* __restrict__ out) {
    __shared__ float s1[D];
    __shared__ float s2[D];
    int row = blockIdx.x;
    int tid = threadIdx.x;
    float v = in[row * D + tid];
    s1[tid] = v;
    s2[tid] = v * v;
    __syncthreads();
    for (int off = D / 2; off > 0; off >>= 1) {
        if (tid < off) {
            s1[tid] += s1[tid + off];
            s2[tid] += s2[tid + off];
        }
        __syncthreads();
    }
    float mean = s1[0] * (1.0f / D);
    float var  = s2[0] * (1.0f / D) - mean * mean;
    float rstd = rsqrtf(var + EPS);
    out[row * D + tid] = (v - mean) * rstd;
}

// ---------------- Tiled GEMM core ----------------
#define BM 64
#define BN 64
#define BK 16

__device__ __forceinline__ void gemm_tile(const float* __restrict__ A, const float* __restrict__ W,
                                          const float* __restrict__ bias, const float* __restrict__ res,
                                          float* __restrict__ C, int N, int K, int act,
                                          int row0, int col0,
                                          float (*As)[BM], float (*Ws)[BN]) {
    int tx = threadIdx.x;       // 0..15
    int ty = threadIdx.y;       // 0..15
    int tid = ty * 16 + tx;     // 0..255

    float acc[4][4];
#pragma unroll
    for (int i = 0; i < 4; i++)
#pragma unroll
        for (int j = 0; j < 4; j++) acc[i][j] = 0.0f;

    int ar = tid >> 2;            // 0..63
    int ac = (tid & 3) << 2;      // 0,4,8,12
    int wr = tid >> 4;            // 0..15
    int wc = (tid & 15) << 2;     // 0..60

    for (int k0 = 0; k0 < K; k0 += BK) {
        float4 a = *(const float4*)&A[(size_t)(row0 + ar) * K + k0 + ac];
        As[ac + 0][ar] = a.x;
        As[ac + 1][ar] = a.y;
        As[ac + 2][ar] = a.z;
        As[ac + 3][ar] = a.w;
        *(float4*)&Ws[wr][wc] = *(const float4*)&W[(size_t)(k0 + wr) * N + col0 + wc];
        __syncthreads();

#pragma unroll
        for (int kk = 0; kk < BK; kk++) {
            float4 a4 = *(float4*)&As[kk][ty * 4];
            float4 b4 = *(float4*)&Ws[kk][tx * 4];
            float av[4] = {a4.x, a4.y, a4.z, a4.w};
            float bv[4] = {b4.x, b4.y, b4.z, b4.w};
#pragma unroll
            for (int i = 0; i < 4; i++)
#pragma unroll
                for (int j = 0; j < 4; j++)
                    acc[i][j] = fmaf(av[i], bv[j], acc[i][j]);
        }
        __syncthreads();
    }

#pragma unroll
    for (int i = 0; i < 4; i++) {
        int r = row0 + ty * 4 + i;
#pragma unroll
        for (int j = 0; j < 4; j++) {
            int c = col0 + tx * 4 + j;
            float val = acc[i][j] + bias[c];
            if (act) val = gelu_tanh(val);
            if (res) val += res[(size_t)r * N + c];
            C[(size_t)r * N + c] = val;
        }
    }
}

__global__ void gemm_kernel(const float* __restrict__ A, const float* __restrict__ W,
                            const float* __restrict__ bias, const float* __restrict__ res,
                            float* __restrict__ C, int N, int K, int act) {
    __shared__ float As[BK][BM];
    __shared__ float Ws[BK][BN];
    gemm_tile(A, W, bias, res, C, N, K, act,
              blockIdx.y * BM, blockIdx.x * BN, As, Ws);
}

// Fused Q/K/V projection: blockIdx.z selects which weight/bias/output
__global__ void qkv_gemm_kernel(const float* __restrict__ A,
                                const float* __restrict__ wq, const float* __restrict__ wk,
                                const float* __restrict__ wv,
                                const float* __restrict__ bq, const float* __restrict__ bk,
                                const float* __restrict__ bv,
                                float* __restrict__ out /* [3][S*D] */) {
    __shared__ float As[BK][BM];
    __shared__ float Ws[BK][BN];
    const float* W;
    const float* bias;
    int z = blockIdx.z;
    if (z == 0)      { W = wq; bias = bq; }
    else if (z == 1) { W = wk; bias = bk; }
    else             { W = wv; bias = bv; }
    float* C = out + (size_t)z * S * D;
    gemm_tile(A, W, bias, nullptr, C, D, D, 0,
              blockIdx.y * BM, blockIdx.x * BN, As, Ws);
}

// ---------------- Sliding-window attention ----------------
// Block = 32 consecutive queries x 8 heads (256 threads). warp = head, lane = query.
// K/V staged in SMEM in 32-key chunks; q and the output accumulator live in registers.
// Two-phase per chunk: all 32 scores -> single online-softmax rescale -> PV.
__global__ void __launch_bounds__(256, 2)
attn_kernel(const float* __restrict__ q, const float* __restrict__ k,
            const float* __restrict__ v, float* __restrict__ o) {
    __shared__ float ks[32][D];   // 32 KB
    __shared__ float vs[32][D];   // 32 KB

    int qb = blockIdx.x * QT;
    int head = threadIdx.x >> 5;
    int lane = threadIdx.x & 31;
    int i = qb + lane;            // this lane's query
    const float scale = 0.17677669529663687f; // 1/sqrt(32)

    // q in registers
    float qr[DH];
    {
        const float* qrow = q + (size_t)i * D + head * DH;
#pragma unroll
        for (int d = 0; d < DH; d += 4) {
            float4 t = *(const float4*)&qrow[d];
            qr[d]   = t.x * scale;
            qr[d+1] = t.y * scale;
            qr[d+2] = t.z * scale;
            qr[d+3] = t.w * scale;
        }
    }

    int kstart = max(0, qb - HALF_WIN);
    int kend   = min(S, qb + QT + HALF_WIN);   // exclusive; both multiples of 32
    int wlo = i - HALF_WIN, whi = i + HALF_WIN;

    float m = -1e30f, l = 0.0f;
    float acc[DH];
#pragma unroll
    for (int d = 0; d < DH; d++) acc[d] = 0.0f;

    for (int c0 = kstart; c0 < kend; c0 += 32) {
        __syncthreads();   // previous chunk fully consumed
        // stage K,V rows [c0, c0+32): 256 threads x 8 float4 per tensor, coalesced
#pragma unroll
        for (int rep = 0; rep < 8; rep++) {
            int idx = threadIdx.x + rep * 256;   // 0..2047
            int r  = idx >> 6;                   // row 0..31
            int c4 = (idx & 63) << 2;            // col 0..252
            *(float4*)&ks[r][c4] = *(const float4*)&k[(size_t)(c0 + r) * D + c4];
            *(float4*)&vs[r][c4] = *(const float4*)&v[(size_t)(c0 + r) * D + c4];
        }
        __syncthreads();

        // phase A: scores
        float s[32];
        float cm = -1e30f;
#pragma unroll
        for (int j = 0; j < 32; j++) {
            int key = c0 + j;
            float dot = 0.0f;
#pragma unroll
            for (int d = 0; d < DH; d += 4) {
                float4 k4 = *(const float4*)&ks[j][head * DH + d];
                dot = fmaf(k4.x, qr[d],   dot);
                dot = fmaf(k4.y, qr[d+1], dot);
                dot = fmaf(k4.z, qr[d+2], dot);
                dot = fmaf(k4.w, qr[d+3], dot);
            }
            bool valid = (key >= wlo) && (key <= whi);
            s[j] = valid ? dot : -1e30f;
            cm = fmaxf(cm, s[j]);
        }

        // single rescale per chunk
        float mn = fmaxf(m, cm);
        float corr = __expf(m - mn);
        l *= corr;
#pragma unroll
        for (int d = 0; d < DH; d++) acc[d] *= corr;
        m = mn;

        // phase B: probabilities + PV
#pragma unroll
        for (int j = 0; j < 32; j++) {
            float p = (s[j] > -1e29f) ? __expf(s[j] - mn) : 0.0f;
            l += p;
#pragma unroll
            for (int d = 0; d < DH; d += 4) {
                float4 v4 = *(const float4*)&vs[j][head * DH + d];
                acc[d]   = fmaf(p, v4.x, acc[d]);
                acc[d+1] = fmaf(p, v4.y, acc[d+1]);
                acc[d+2] = fmaf(p, v4.z, acc[d+2]);
                acc[d+3] = fmaf(p, v4.w, acc[d+3]);
            }
        }
    }

    float inv = 1.0f / l;
    float* orow = o + (size_t)i * D + head * DH;
#pragma unroll
    for (int d = 0; d < DH; d += 4) {
        float4 t;
        t.x = acc[d]   * inv;
        t.y = acc[d+1] * inv;
        t.z = acc[d+2] * inv;
        t.w = acc[d+3] * inv;
        *(float4*)&orow[d] = t;
    }
}

// ---------------- launch ----------------
extern "C" void kernel_launch(void* const* d_in, const int* in_sizes, int n_in,
                              void* d_out, int out_size) {
    const float* x  = (const float*)d_in[0];
    const float* wq = (const float*)d_in[1];
    const float* bq = (const float*)d_in[2];
    const float* wk = (const float*)d_in[3];
    const float* bk = (const float*)d_in[4];
    const float* wv = (const float*)d_in[5];
    const float* bv = (const float*)d_in[6];
    const float* wo = (const float*)d_in[7];
    const float* bo = (const float*)d_in[8];
    const float* w1 = (const float*)d_in[9];
    const float* b1 = (const float*)d_in[10];
    const float* w2 = (const float*)d_in[11];
    const float* b2 = (const float*)d_in[12];

    float* h = (float*)d_out;   // residual stream lives in the output buffer

    float *n, *qkv, *o, *ff;
    cudaGetSymbolAddress((void**)&n,   g_n);
    cudaGetSymbolAddress((void**)&qkv, g_qkv);
    cudaGetSymbolAddress((void**)&o,   g_o);
    cudaGetSymbolAddress((void**)&ff,  g_ff);
    float* q = qkv;
    float* k = qkv + (size_t)S * D;
    float* v = qkv + (size_t)2 * S * D;

    // h = x
    copy_kernel<<<(S * D + 255) / 256, 256>>>(x, h, S * D);

    dim3 tb(16, 16);
    dim3 grid_d(D / BN, S / BM);        // 4 x 64
    dim3 grid_qkv(D / BN, S / BM, 3);   // fused q,k,v
    dim3 grid_f(FF / BN, S / BM);       // 16 x 64

    for (int l = 0; l < NLAYERS; l++) {
        const float* lwq = wq + (size_t)l * D * D;
        const float* lwk = wk + (size_t)l * D * D;
        const float* lwv = wv + (size_t)l * D * D;
        const float* lwo = wo + (size_t)l * D * D;
        const float* lw1 = w1 + (size_t)l * D * FF;
        const float* lw2 = w2 + (size_t)l * FF * D;
        const float* lbq = bq + (size_t)l * D;
        const float* lbk = bk + (size_t)l * D;
        const float* lbv = bv + (size_t)l * D;
        const float* lbo = bo + (size_t)l * D;
        const float* lb1 = b1 + (size_t)l * FF;
        const float* lb2 = b2 + (size_t)l * D;

        // n = LN(h)
        ln_kernel<<<S, D>>>(h, n);
        // q,k,v = n @ W + b  (one fused launch, 768 blocks)
        qkv_gemm_kernel<<<grid_qkv, tb>>>(n, lwq, lwk, lwv, lbq, lbk, lbv, qkv);
        // o = sliding-window attention
        attn_kernel<<<S / QT, 256>>>(q, k, v, o);
        // h = h + o @ wo + bo
        gemm_kernel<<<grid_d, tb>>>(o, lwo, lbo, h, h, D, D, 0);
        // h = LN(h) (in place)
        ln_kernel<<<S, D>>>(h, h);
        // ff = gelu(h @ w1 + b1)
        gemm_kernel<<<grid_f, tb>>>(h, lw1, lb1, nullptr, ff, FF, D, 1);
        // h = h + ff @ w2 + b2
        gemm_kernel<<<grid_d, tb>>>(ff, lw2, lb2, h, h, D, FF, 0);
    }
}

// round 6
// speedup vs baseline: 2.5587x; 1.1352x over previous
#include <cuda_runtime.h>
#include <cuda_bf16.h>
#include <math.h>

// Problem constants
#define S 4096
#define D 256
#define HEADS 8
#define DH 32
#define FF 1024
#define NLAYERS 4
#define HALF_WIN 256
#define EPS 1e-5f
#define QT 16            // queries per attention block

// ---------------- scratch (device globals, no allocation allowed) ----------------
__device__ float g_n  [S * D];
__device__ float g_qkv[3 * S * D];
__device__ float g_o  [S * D];
__device__ float g_ff [S * FF];

// ---------------- helpers ----------------
__device__ __forceinline__ float gelu_tanh(float x) {
    const float c = 0.7978845608028654f; // sqrt(2/pi)
    float x3 = x * x * x;
    float t = tanhf(c * (x + 0.044715f * x3));
    return 0.5f * x * (1.0f + t);
}

// ---------------- copy ----------------
__global__ void copy_kernel(const float* __restrict__ in, float* __restrict__ out, int n) {
    int i = blockIdx.x * blockDim.x + threadIdx.x;
    if (i < n) out[i] = in[i];
}

// ---------------- LayerNorm (no affine), one block per row of D=256 ----------------
__global__ void ln_kernel(const float* __restrict__ in, float* __restrict__ out) {
    __shared__ float s1[D];
    __shared__ float s2[D];
    int row = blockIdx.x;
    int tid = threadIdx.x;
    float v = in[row * D + tid];
    s1[tid] = v;
    s2[tid] = v * v;
    __syncthreads();
    for (int off = D / 2; off > 0; off >>= 1) {
        if (tid < off) {
            s1[tid] += s1[tid + off];
            s2[tid] += s2[tid + off];
        }
        __syncthreads();
    }
    float mean = s1[0] * (1.0f / D);
    float var  = s2[0] * (1.0f / D) - mean * mean;
    float rstd = rsqrtf(var + EPS);
    out[row * D + tid] = (v - mean) * rstd;
}

// ---------------- Tiled GEMM core: 128x64 tile, BK=16, double-buffered ----------------
#define BM 128
#define BN 64
#define BK 16

// As stored transposed: As[buf][k][m]; Ws row-major: Ws[buf][k][n].
__device__ __forceinline__ void gemm_tile(const float* __restrict__ A, const float* __restrict__ W,
                                          const float* __restrict__ bias, const float* __restrict__ res,
                                          float* __restrict__ C, int N, int K, int act,
                                          int row0, int col0,
                                          float (*As)[BK][BM], float (*Ws)[BK][BN]) {
    int tid = threadIdx.x;            // 0..255
    int tx  = tid & 15;               // 0..15  (N dir, 4 cols each)
    int ty  = tid >> 4;               // 0..15  (M dir, 8 rows each)

    // A loads: 512 float4 per tile -> 2 per thread
    int ar = tid >> 2;                // 0..63 (also ar+64)
    int ac = (tid & 3) << 2;          // k offset 0,4,8,12
    // W loads: 256 float4 per tile -> 1 per thread
    int wr = tid >> 4;                // 0..15
    int wc = (tid & 15) << 2;         // 0..60

    float acc[8][4];
#pragma unroll
    for (int i = 0; i < 8; i++)
#pragma unroll
        for (int j = 0; j < 4; j++) acc[i][j] = 0.0f;

    const float* Arow0 = A + (size_t)(row0 + ar) * K;
    const float* Arow1 = A + (size_t)(row0 + ar + 64) * K;

    // prologue: tile 0 -> buffer 0
    {
        float4 a0 = *(const float4*)&Arow0[ac];
        float4 a1 = *(const float4*)&Arow1[ac];
        As[0][ac + 0][ar] = a0.x; As[0][ac + 1][ar] = a0.y;
        As[0][ac + 2][ar] = a0.z; As[0][ac + 3][ar] = a0.w;
        As[0][ac + 0][ar + 64] = a1.x; As[0][ac + 1][ar + 64] = a1.y;
        As[0][ac + 2][ar + 64] = a1.z; As[0][ac + 3][ar + 64] = a1.w;
        *(float4*)&Ws[0][wr][wc] = *(const float4*)&W[(size_t)wr * N + col0 + wc];
    }
    __syncthreads();

    int nk = K / BK;
    for (int t = 0; t < nk; t++) {
        int cur = t & 1;
        float4 pa0, pa1, pw;
        if (t + 1 < nk) {
            int kb = (t + 1) * BK;
            pa0 = *(const float4*)&Arow0[kb + ac];
            pa1 = *(const float4*)&Arow1[kb + ac];
            pw  = *(const float4*)&W[(size_t)(kb + wr) * N + col0 + wc];
        }

#pragma unroll
        for (int kk = 0; kk < BK; kk++) {
            float4 aA = *(float4*)&As[cur][kk][ty * 8];
            float4 aB = *(float4*)&As[cur][kk][ty * 8 + 4];
            float4 b  = *(float4*)&Ws[cur][kk][tx * 4];
            float av[8] = {aA.x, aA.y, aA.z, aA.w, aB.x, aB.y, aB.z, aB.w};
            float bv[4] = {b.x, b.y, b.z, b.w};
#pragma unroll
            for (int i = 0; i < 8; i++)
#pragma unroll
                for (int j = 0; j < 4; j++)
                    acc[i][j] = fmaf(av[i], bv[j], acc[i][j]);
        }

        if (t + 1 < nk) {
            int nxt = cur ^ 1;
            As[nxt][ac + 0][ar] = pa0.x; As[nxt][ac + 1][ar] = pa0.y;
            As[nxt][ac + 2][ar] = pa0.z; As[nxt][ac + 3][ar] = pa0.w;
            As[nxt][ac + 0][ar + 64] = pa1.x; As[nxt][ac + 1][ar + 64] = pa1.y;
            As[nxt][ac + 2][ar + 64] = pa1.z; As[nxt][ac + 3][ar + 64] = pa1.w;
            *(float4*)&Ws[nxt][wr][wc] = pw;
        }
        __syncthreads();
    }

#pragma unroll
    for (int i = 0; i < 8; i++) {
        int r = row0 + ty * 8 + i;
        float* crow = C + (size_t)r * N + col0 + tx * 4;
        const float* rrow = res ? res + (size_t)r * N + col0 + tx * 4 : nullptr;
        float4 out;
        float vals[4];
#pragma unroll
        for (int j = 0; j < 4; j++) {
            float val = acc[i][j] + bias[col0 + tx * 4 + j];
            if (act) val = gelu_tanh(val);
            vals[j] = val;
        }
        if (rrow) {
            float4 rv = *(const float4*)rrow;
            vals[0] += rv.x; vals[1] += rv.y; vals[2] += rv.z; vals[3] += rv.w;
        }
        out.x = vals[0]; out.y = vals[1]; out.z = vals[2]; out.w = vals[3];
        *(float4*)crow = out;
    }
}

__global__ void __launch_bounds__(256) gemm_kernel(
        const float* __restrict__ A, const float* __restrict__ W,
        const float* __restrict__ bias, const float* __restrict__ res,
        float* __restrict__ C, int N, int K, int act) {
    __shared__ float As[2][BK][BM];
    __shared__ float Ws[2][BK][BN];
    gemm_tile(A, W, bias, res, C, N, K, act,
              blockIdx.y * BM, blockIdx.x * BN, As, Ws);
}

// Fused Q/K/V projection: blockIdx.z selects which weight/bias/output
__global__ void __launch_bounds__(256) qkv_gemm_kernel(
        const float* __restrict__ A,
        const float* __restrict__ wq, const float* __restrict__ wk,
        const float* __restrict__ wv,
        const float* __restrict__ bq, const float* __restrict__ bk,
        const float* __restrict__ bv,
        float* __restrict__ out /* [3][S*D] */) {
    __shared__ float As[2][BK][BM];
    __shared__ float Ws[2][BK][BN];
    const float* W;
    const float* bias;
    int z = blockIdx.z;
    if (z == 0)      { W = wq; bias = bq; }
    else if (z == 1) { W = wk; bias = bk; }
    else             { W = wv; bias = bv; }
    float* C = out + (size_t)z * S * D;
    gemm_tile(A, W, bias, nullptr, C, D, D, 0,
              blockIdx.y * BM, blockIdx.x * BN, As, Ws);
}

// ---------------- Sliding-window attention ----------------
// Block = 16 queries x 8 heads (256 threads, grid = S/16 = 256 blocks).
// warp = head. lane = (query in 0..15) + 16 * (key half).
// 32-key K/V chunks staged in SMEM; each half-warp handles 16 keys of the chunk;
// per-lane online softmax states merged across the half-warps at the end.
__global__ void __launch_bounds__(256, 2)
attn_kernel(const float* __restrict__ q, const float* __restrict__ k,
            const float* __restrict__ v, float* __restrict__ o) {
    __shared__ float ks[32][D];   // 32 KB
    __shared__ float vs[32][D];   // 32 KB

    int qb = blockIdx.x * QT;
    int head = threadIdx.x >> 5;
    int lane = threadIdx.x & 31;
    int ql = lane & 15;           // query within block
    int kh = lane >> 4;           // which 16-key half of each chunk
    int i = qb + ql;              // this lane's query
    const float scale = 0.17677669529663687f; // 1/sqrt(32)

    // q in registers
    float qr[DH];
    {
        const float* qrow = q + (size_t)i * D + head * DH;
#pragma unroll
        for (int d = 0; d < DH; d += 4) {
            float4 t = *(const float4*)&qrow[d];
            qr[d]   = t.x * scale;
            qr[d+1] = t.y * scale;
            qr[d+2] = t.z * scale;
            qr[d+3] = t.w * scale;
        }
    }

    int kstart = max(0, qb - HALF_WIN);
    int kend   = min(S, qb + QT + HALF_WIN);   // exclusive
    int wlo = i - HALF_WIN, whi = i + HALF_WIN;

    float m = -1e30f, l = 0.0f;
    float acc[DH];
#pragma unroll
    for (int d = 0; d < DH; d++) acc[d] = 0.0f;

    for (int c0 = kstart; c0 < kend; c0 += 32) {
        __syncthreads();   // previous chunk fully consumed
        // stage K,V rows [c0, c0+32): 256 threads x 8 float4 per tensor
#pragma unroll
        for (int rep = 0; rep < 8; rep++) {
            int idx = threadIdx.x + rep * 256;   // 0..2047
            int r  = idx >> 6;                   // row 0..31
            int c4 = (idx & 63) << 2;            // col 0..252
            int grow = c0 + r;
            if (grow < S) {
                *(float4*)&ks[r][c4] = *(const float4*)&k[(size_t)grow * D + c4];
                *(float4*)&vs[r][c4] = *(const float4*)&v[(size_t)grow * D + c4];
            } else {
                float4 z = {0.f, 0.f, 0.f, 0.f};
                *(float4*)&ks[r][c4] = z;
                *(float4*)&vs[r][c4] = z;
            }
        }
        __syncthreads();

        // phase A: 16 scores for this half-warp's keys
        float s[16];
        float cm = -1e30f;
#pragma unroll
        for (int j = 0; j < 16; j++) {
            int row = kh * 16 + j;
            int key = c0 + row;
            float d0 = 0.f, d1 = 0.f, d2 = 0.f, d3 = 0.f;
            const float* krow = &ks[row][head * DH];
            {
                float4 k0 = *(const float4*)&krow[0];
                float4 k1 = *(const float4*)&krow[4];
                float4 k2 = *(const float4*)&krow[8];
                float4 k3 = *(const float4*)&krow[12];
                d0 = fmaf(k0.x, qr[0], d0);  d0 = fmaf(k0.y, qr[1], d0);
                d0 = fmaf(k0.z, qr[2], d0);  d0 = fmaf(k0.w, qr[3], d0);
                d1 = fmaf(k1.x, qr[4], d1);  d1 = fmaf(k1.y, qr[5], d1);
                d1 = fmaf(k1.z, qr[6], d1);  d1 = fmaf(k1.w, qr[7], d1);
                d2 = fmaf(k2.x, qr[8], d2);  d2 = fmaf(k2.y, qr[9], d2);
                d2 = fmaf(k2.z, qr[10], d2); d2 = fmaf(k2.w, qr[11], d2);
                d3 = fmaf(k3.x, qr[12], d3); d3 = fmaf(k3.y, qr[13], d3);
                d3 = fmaf(k3.z, qr[14], d3); d3 = fmaf(k3.w, qr[15], d3);
            }
            {
                float4 k0 = *(const float4*)&krow[16];
                float4 k1 = *(const float4*)&krow[20];
                float4 k2 = *(const float4*)&krow[24];
                float4 k3 = *(const float4*)&krow[28];
                d0 = fmaf(k0.x, qr[16], d0); d0 = fmaf(k0.y, qr[17], d0);
                d0 = fmaf(k0.z, qr[18], d0); d0 = fmaf(k0.w, qr[19], d0);
                d1 = fmaf(k1.x, qr[20], d1); d1 = fmaf(k1.y, qr[21], d1);
                d1 = fmaf(k1.z, qr[22], d1); d1 = fmaf(k1.w, qr[23], d1);
                d2 = fmaf(k2.x, qr[24], d2); d2 = fmaf(k2.y, qr[25], d2);
                d2 = fmaf(k2.z, qr[26], d2); d2 = fmaf(k2.w, qr[27], d2);
                d3 = fmaf(k3.x, qr[28], d3); d3 = fmaf(k3.y, qr[29], d3);
                d3 = fmaf(k3.z, qr[30], d3); d3 = fmaf(k3.w, qr[31], d3);
            }
            float dot = (d0 + d1) + (d2 + d3);
            bool valid = (key >= wlo) && (key <= whi) && (key < S);
            s[j] = valid ? dot : -1e30f;
            cm = fmaxf(cm, s[j]);
        }

        // single rescale per chunk (per half-warp state)
        float mn = fmaxf(m, cm);
        float corr = __expf(m - mn);
        l *= corr;
#pragma unroll
        for (int d = 0; d < DH; d++) acc[d] *= corr;
        m = mn;

        // phase B: probabilities + PV over this half's 16 keys
#pragma unroll
        for (int j = 0; j < 16; j++) {
            float p = (s[j] > -1e29f) ? __expf(s[j] - mn) : 0.0f;
            l += p;
            const float* vrow = &vs[kh * 16 + j][head * DH];
#pragma unroll
            for (int d = 0; d < DH; d += 4) {
                float4 v4 = *(const float4*)&vrow[d];
                acc[d]   = fmaf(p, v4.x, acc[d]);
                acc[d+1] = fmaf(p, v4.y, acc[d+1]);
                acc[d+2] = fmaf(p, v4.z, acc[d+2]);
                acc[d+3] = fmaf(p, v4.w, acc[d+3]);
            }
        }
    }

    // merge the two half-warp softmax states (lane <-> lane^16 hold same query)
    float m2 = __shfl_xor_sync(0xffffffffu, m, 16);
    float l2 = __shfl_xor_sync(0xffffffffu, l, 16);
    float mn = fmaxf(m, m2);
    float c1 = __expf(m - mn);
    float c2 = __expf(m2 - mn);
    float lt = l * c1 + l2 * c2;
    float inv = 1.0f / lt;

    float outv[DH];
#pragma unroll
    for (int d = 0; d < DH; d++) {
        float a2 = __shfl_xor_sync(0xffffffffu, acc[d], 16);
        outv[d] = (acc[d] * c1 + a2 * c2) * inv;
    }

    if (kh == 0) {
        float* orow = o + (size_t)i * D + head * DH;
#pragma unroll
        for (int d = 0; d < DH; d += 4) {
            float4 t = {outv[d], outv[d+1], outv[d+2], outv[d+3]};
            *(float4*)&orow[d] = t;
        }
    }
}

// ---------------- launch ----------------
extern "C" void kernel_launch(void* const* d_in, const int* in_sizes, int n_in,
                              void* d_out, int out_size) {
    const float* x  = (const float*)d_in[0];
    const float* wq = (const float*)d_in[1];
    const float* bq = (const float*)d_in[2];
    const float* wk = (const float*)d_in[3];
    const float* bk = (const float*)d_in[4];
    const float* wv = (const float*)d_in[5];
    const float* bv = (const float*)d_in[6];
    const float* wo = (const float*)d_in[7];
    const float* bo = (const float*)d_in[8];
    const float* w1 = (const float*)d_in[9];
    const float* b1 = (const float*)d_in[10];
    const float* w2 = (const float*)d_in[11];
    const float* b2 = (const float*)d_in[12];

    float* h = (float*)d_out;   // residual stream lives in the output buffer

    float *n, *qkv, *o, *ff;
    cudaGetSymbolAddress((void**)&n,   g_n);
    cudaGetSymbolAddress((void**)&qkv, g_qkv);
    cudaGetSymbolAddress((void**)&o,   g_o);
    cudaGetSymbolAddress((void**)&ff,  g_ff);
    float* q = qkv;
    float* k = qkv + (size_t)S * D;
    float* v = qkv + (size_t)2 * S * D;

    // h = x
    copy_kernel<<<(S * D + 255) / 256, 256>>>(x, h, S * D);

    dim3 grid_d(D / BN, S / BM);        // 4 x 32
    dim3 grid_qkv(D / BN, S / BM, 3);   // fused q,k,v: 384 blocks
    dim3 grid_f(FF / BN, S / BM);       // 16 x 32

    for (int l = 0; l < NLAYERS; l++) {
        const float* lwq = wq + (size_t)l * D * D;
        const float* lwk = wk + (size_t)l * D * D;
        const float* lwv = wv + (size_t)l * D * D;
        const float* lwo = wo + (size_t)l * D * D;
        const float* lw1 = w1 + (size_t)l * D * FF;
        const float* lw2 = w2 + (size_t)l * FF * D;
        const float* lbq = bq + (size_t)l * D;
        const float* lbk = bk + (size_t)l * D;
        const float* lbv = bv + (size_t)l * D;
        const float* lbo = bo + (size_t)l * D;
        const float* lb1 = b1 + (size_t)l * FF;
        const float* lb2 = b2 + (size_t)l * D;

        // n = LN(h)
        ln_kernel<<<S, D>>>(h, n);
        // q,k,v = n @ W + b  (one fused launch)
        qkv_gemm_kernel<<<grid_qkv, 256>>>(n, lwq, lwk, lwv, lbq, lbk, lbv, qkv);
        // o = sliding-window attention
        attn_kernel<<<S / QT, 256>>>(q, k, v, o);
        // h = h + o @ wo + bo
        gemm_kernel<<<grid_d, 256>>>(o, lwo, lbo, h, h, D, D, 0);
        // h = LN(h) (in place)
        ln_kernel<<<S, D>>>(h, h);
        // ff = gelu(h @ w1 + b1)
        gemm_kernel<<<grid_f, 256>>>(h, lw1, lb1, nullptr, ff, FF, D, 1);
        // h = h + ff @ w2 + b2
        gemm_kernel<<<grid_d, 256>>>(ff, lw2, lb2, h, h, D, FF, 0);
    }
}

// round 8
// speedup vs baseline: 3.5738x; 1.3967x over previous
#include <cuda_runtime.h>
#include <cuda_bf16.h>
#include <math.h>
#include <stdint.h>

// Problem constants
#define S 4096
#define D 256
#define HEADS 8
#define DH 32
#define FF 1024
#define NLAYERS 4
#define HALF_WIN 256
#define EPS 1e-5f
#define QT 16            // queries per attention block

// ---------------- scratch (device globals, no allocation allowed) ----------------
__device__ float g_n  [S * D];
__device__ float g_qkv[3 * S * D];
__device__ float g_o  [S * D];
__device__ float g_ff [S * FF];

// ---------------- helpers ----------------
__device__ __forceinline__ float gelu_tanh(float x) {
    const float c = 0.7978845608028654f; // sqrt(2/pi)
    float x3 = x * x * x;
    float t = tanhf(c * (x + 0.044715f * x3));
    return 0.5f * x * (1.0f + t);
}

__device__ __forceinline__ uint32_t f2tf(float f) {
    uint32_t u;
    asm("cvt.rna.tf32.f32 %0, %1;" : "=r"(u) : "f"(f));
    return u;
}

__device__ __forceinline__ void mma_tf32(float c[4], const uint32_t a[4],
                                         uint32_t b0, uint32_t b1) {
    asm volatile(
        "mma.sync.aligned.m16n8k8.row.col.f32.tf32.tf32.f32 "
        "{%0,%1,%2,%3}, {%4,%5,%6,%7}, {%8,%9}, {%0,%1,%2,%3};\n"
        : "+f"(c[0]), "+f"(c[1]), "+f"(c[2]), "+f"(c[3])
        : "r"(a[0]), "r"(a[1]), "r"(a[2]), "r"(a[3]), "r"(b0), "r"(b1));
}

// ---------------- copy ----------------
__global__ void copy_kernel(const float* __restrict__ in, float* __restrict__ out, int n) {
    int i = blockIdx.x * blockDim.x + threadIdx.x;
    if (i < n) out[i] = in[i];
}

// ---------------- LayerNorm: warp per row, 8 rows per block ----------------
__global__ void ln_kernel(const float* __restrict__ in, float* __restrict__ out) {
    int warp = threadIdx.x >> 5;
    int lane = threadIdx.x & 31;
    int row = blockIdx.x * 8 + warp;
    const float* rp = in + (size_t)row * D + lane * 8;
    float4 v0 = *(const float4*)&rp[0];
    float4 v1 = *(const float4*)&rp[4];
    float s1 = v0.x + v0.y + v0.z + v0.w + v1.x + v1.y + v1.z + v1.w;
    float s2 = v0.x*v0.x + v0.y*v0.y + v0.z*v0.z + v0.w*v0.w
             + v1.x*v1.x + v1.y*v1.y + v1.z*v1.z + v1.w*v1.w;
#pragma unroll
    for (int off = 16; off > 0; off >>= 1) {
        s1 += __shfl_xor_sync(0xffffffffu, s1, off);
        s2 += __shfl_xor_sync(0xffffffffu, s2, off);
    }
    float mean = s1 * (1.0f / D);
    float var  = s2 * (1.0f / D) - mean * mean;
    float rstd = rsqrtf(var + EPS);
    float* op = out + (size_t)row * D + lane * 8;
    float4 o0, o1;
    o0.x = (v0.x - mean) * rstd; o0.y = (v0.y - mean) * rstd;
    o0.z = (v0.z - mean) * rstd; o0.w = (v0.w - mean) * rstd;
    o1.x = (v1.x - mean) * rstd; o1.y = (v1.y - mean) * rstd;
    o1.z = (v1.z - mean) * rstd; o1.w = (v1.w - mean) * rstd;
    *(float4*)&op[0] = o0;
    *(float4*)&op[4] = o1;
}

// ---------------- tf32 tensor-core GEMM: 128x64 tile, BK=16, double-buffered ----------------
#define BM 128
#define BN 64
#define BKT 16
#define AP 20     // As row pitch (u32)
#define BP 72     // Bs row pitch (u32)

// C[M,N] = A[M,K] @ W[K,N] + bias (+gelu) (+res)
__device__ __forceinline__ void gemm_tile_tc(
        const float* __restrict__ A, const float* __restrict__ W,
        const float* __restrict__ bias, const float* __restrict__ res,
        float* __restrict__ C, int N, int K, int act,
        int row0, int col0,
        uint32_t (*As)[BM][AP], uint32_t (*Bs)[BKT][BP]) {
    int tid  = threadIdx.x;
    int warp = tid >> 5;
    int lane = tid & 31;
    int g    = lane >> 2;     // group id 0..7
    int tig  = lane & 3;      // thread in group 0..3
    int wm   = warp & 3;      // warp M index (0..3)
    int wn   = warp >> 2;     // warp N index (0..1)

    // A staging: 128 rows x 16 cols = 512 float4; 2 per thread (rows ar, ar+64)
    int ar = tid >> 2;            // 0..63
    int ac = (tid & 3) << 2;      // 0,4,8,12
    // B staging: 16 rows x 64 cols = 256 float4; 1 per thread
    int br = tid >> 4;            // 0..15
    int bc = (tid & 15) << 2;     // 0..60

    float acc[2][4][4];
#pragma unroll
    for (int mi = 0; mi < 2; mi++)
#pragma unroll
        for (int ni = 0; ni < 4; ni++)
#pragma unroll
            for (int r = 0; r < 4; r++) acc[mi][ni][r] = 0.0f;

    const float* Ar0 = A + (size_t)(row0 + ar) * K;
    const float* Ar1 = A + (size_t)(row0 + ar + 64) * K;

    // prologue: stage tile 0 -> buffer 0
    {
        float4 a0 = *(const float4*)&Ar0[ac];
        float4 a1 = *(const float4*)&Ar1[ac];
        float4 b  = *(const float4*)&W[(size_t)br * N + col0 + bc];
        uint4 ua0 = {f2tf(a0.x), f2tf(a0.y), f2tf(a0.z), f2tf(a0.w)};
        uint4 ua1 = {f2tf(a1.x), f2tf(a1.y), f2tf(a1.z), f2tf(a1.w)};
        uint4 ub  = {f2tf(b.x),  f2tf(b.y),  f2tf(b.z),  f2tf(b.w)};
        *(uint4*)&As[0][ar][ac]      = ua0;
        *(uint4*)&As[0][ar + 64][ac] = ua1;
        *(uint4*)&Bs[0][br][bc]      = ub;
    }
    __syncthreads();

    int nk = K / BKT;
    for (int t = 0; t < nk; t++) {
        int cur = t & 1;
        float4 pa0, pa1, pb;
        if (t + 1 < nk) {
            int kb = (t + 1) * BKT;
            pa0 = *(const float4*)&Ar0[kb + ac];
            pa1 = *(const float4*)&Ar1[kb + ac];
            pb  = *(const float4*)&W[(size_t)(kb + br) * N + col0 + bc];
        }

#pragma unroll
        for (int ks = 0; ks < 2; ks++) {
            uint32_t a[2][4];
#pragma unroll
            for (int mi = 0; mi < 2; mi++) {
                int r = wm * 32 + mi * 16 + g;
                int kbn = ks * 8 + tig;
                a[mi][0] = As[cur][r][kbn];
                a[mi][1] = As[cur][r + 8][kbn];
                a[mi][2] = As[cur][r][kbn + 4];
                a[mi][3] = As[cur][r + 8][kbn + 4];
            }
#pragma unroll
            for (int ni = 0; ni < 4; ni++) {
                int cn = wn * 32 + ni * 8 + g;
                uint32_t b0 = Bs[cur][ks * 8 + tig][cn];
                uint32_t b1 = Bs[cur][ks * 8 + tig + 4][cn];
                mma_tf32(acc[0][ni], a[0], b0, b1);
                mma_tf32(acc[1][ni], a[1], b0, b1);
            }
        }

        if (t + 1 < nk) {
            int nxt = cur ^ 1;
            uint4 ua0 = {f2tf(pa0.x), f2tf(pa0.y), f2tf(pa0.z), f2tf(pa0.w)};
            uint4 ua1 = {f2tf(pa1.x), f2tf(pa1.y), f2tf(pa1.z), f2tf(pa1.w)};
            uint4 ub  = {f2tf(pb.x),  f2tf(pb.y),  f2tf(pb.z),  f2tf(pb.w)};
            *(uint4*)&As[nxt][ar][ac]      = ua0;
            *(uint4*)&As[nxt][ar + 64][ac] = ua1;
            *(uint4*)&Bs[nxt][br][bc]      = ub;
        }
        __syncthreads();
    }

    // epilogue: each thread owns rows {g, g+8} x cols {tig*2, tig*2+1} per fragment
#pragma unroll
    for (int mi = 0; mi < 2; mi++) {
#pragma unroll
        for (int ni = 0; ni < 4; ni++) {
            int r  = row0 + wm * 32 + mi * 16 + g;
            int cc = col0 + wn * 32 + ni * 8 + tig * 2;
            float b0 = __ldg(&bias[cc]);
            float b1 = __ldg(&bias[cc + 1]);
#pragma unroll
            for (int half = 0; half < 2; half++) {
                int rr = r + half * 8;
                float v0 = acc[mi][ni][half * 2 + 0] + b0;
                float v1 = acc[mi][ni][half * 2 + 1] + b1;
                if (act) { v0 = gelu_tanh(v0); v1 = gelu_tanh(v1); }
                if (res) {
                    float2 rv = *(const float2*)&res[(size_t)rr * N + cc];
                    v0 += rv.x; v1 += rv.y;
                }
                float2 ov = {v0, v1};
                *(float2*)&C[(size_t)rr * N + cc] = ov;
            }
        }
    }
}

__global__ void __launch_bounds__(256) gemm_kernel(
        const float* __restrict__ A, const float* __restrict__ W,
        const float* __restrict__ bias, const float* __restrict__ res,
        float* __restrict__ C, int N, int K, int act) {
    __shared__ uint32_t As[2][BM][AP];
    __shared__ uint32_t Bs[2][BKT][BP];
    gemm_tile_tc(A, W, bias, res, C, N, K, act,
                 blockIdx.y * BM, blockIdx.x * BN, As, Bs);
}

__global__ void __launch_bounds__(256) qkv_gemm_kernel(
        const float* __restrict__ A,
        const float* __restrict__ wq, const float* __restrict__ wk,
        const float* __restrict__ wv,
        const float* __restrict__ bq, const float* __restrict__ bk,
        const float* __restrict__ bv,
        float* __restrict__ out /* [3][S*D] */) {
    __shared__ uint32_t As[2][BM][AP];
    __shared__ uint32_t Bs[2][BKT][BP];
    const float* W;
    const float* bias;
    int z = blockIdx.z;
    if (z == 0)      { W = wq; bias = bq; }
    else if (z == 1) { W = wk; bias = bk; }
    else             { W = wv; bias = bv; }
    float* C = out + (size_t)z * S * D;
    gemm_tile_tc(A, W, bias, nullptr, C, D, D, 0,
                 blockIdx.y * BM, blockIdx.x * BN, As, Bs);
}

// ---------------- Sliding-window attention ----------------
// Block = 16 queries x 8 heads (256 threads, grid = 256).
// warp = head. lane = (query 0..15) + 16*(key half). Half-warp states merged at end.
__global__ void __launch_bounds__(256, 2)
attn_kernel(const float* __restrict__ q, const float* __restrict__ k,
            const float* __restrict__ v, float* __restrict__ o) {
    __shared__ float ks[32][D];
    __shared__ float vs[32][D];

    int qb = blockIdx.x * QT;
    int head = threadIdx.x >> 5;
    int lane = threadIdx.x & 31;
    int ql = lane & 15;
    int kh = lane >> 4;
    int i = qb + ql;
    const float scale = 0.17677669529663687f;

    float qr[DH];
    {
        const float* qrow = q + (size_t)i * D + head * DH;
#pragma unroll
        for (int d = 0; d < DH; d += 4) {
            float4 t = *(const float4*)&qrow[d];
            qr[d]   = t.x * scale;
            qr[d+1] = t.y * scale;
            qr[d+2] = t.z * scale;
            qr[d+3] = t.w * scale;
        }
    }

    int kstart = max(0, qb - HALF_WIN);
    int kend   = min(S, qb + QT + HALF_WIN);
    int wlo = i - HALF_WIN, whi = i + HALF_WIN;

    float m = -1e30f, l = 0.0f;
    float acc[DH];
#pragma unroll
    for (int d = 0; d < DH; d++) acc[d] = 0.0f;

    for (int c0 = kstart; c0 < kend; c0 += 32) {
        __syncthreads();
#pragma unroll
        for (int rep = 0; rep < 8; rep++) {
            int idx = threadIdx.x + rep * 256;
            int r  = idx >> 6;
            int c4 = (idx & 63) << 2;
            int grow = c0 + r;
            if (grow < S) {
                *(float4*)&ks[r][c4] = *(const float4*)&k[(size_t)grow * D + c4];
                *(float4*)&vs[r][c4] = *(const float4*)&v[(size_t)grow * D + c4];
            } else {
                float4 z = {0.f, 0.f, 0.f, 0.f};
                *(float4*)&ks[r][c4] = z;
                *(float4*)&vs[r][c4] = z;
            }
        }
        __syncthreads();

        float s[16];
        float cm = -1e30f;
#pragma unroll
        for (int j = 0; j < 16; j++) {
            int row = kh * 16 + j;
            int key = c0 + row;
            float d0 = 0.f, d1 = 0.f, d2 = 0.f, d3 = 0.f;
            const float* krow = &ks[row][head * DH];
            {
                float4 k0 = *(const float4*)&krow[0];
                float4 k1 = *(const float4*)&krow[4];
                float4 k2 = *(const float4*)&krow[8];
                float4 k3 = *(const float4*)&krow[12];
                d0 = fmaf(k0.x, qr[0], d0);  d0 = fmaf(k0.y, qr[1], d0);
                d0 = fmaf(k0.z, qr[2], d0);  d0 = fmaf(k0.w, qr[3], d0);
                d1 = fmaf(k1.x, qr[4], d1);  d1 = fmaf(k1.y, qr[5], d1);
                d1 = fmaf(k1.z, qr[6], d1);  d1 = fmaf(k1.w, qr[7], d1);
                d2 = fmaf(k2.x, qr[8], d2);  d2 = fmaf(k2.y, qr[9], d2);
                d2 = fmaf(k2.z, qr[10], d2); d2 = fmaf(k2.w, qr[11], d2);
                d3 = fmaf(k3.x, qr[12], d3); d3 = fmaf(k3.y, qr[13], d3);
                d3 = fmaf(k3.z, qr[14], d3); d3 = fmaf(k3.w, qr[15], d3);
            }
            {
                float4 k0 = *(const float4*)&krow[16];
                float4 k1 = *(const float4*)&krow[20];
                float4 k2 = *(const float4*)&krow[24];
                float4 k3 = *(const float4*)&krow[28];
                d0 = fmaf(k0.x, qr[16], d0); d0 = fmaf(k0.y, qr[17], d0);
                d0 = fmaf(k0.z, qr[18], d0); d0 = fmaf(k0.w, qr[19], d0);
                d1 = fmaf(k1.x, qr[20], d1); d1 = fmaf(k1.y, qr[21], d1);
                d1 = fmaf(k1.z, qr[22], d1); d1 = fmaf(k1.w, qr[23], d1);
                d2 = fmaf(k2.x, qr[24], d2); d2 = fmaf(k2.y, qr[25], d2);
                d2 = fmaf(k2.z, qr[26], d2); d2 = fmaf(k2.w, qr[27], d2);
                d3 = fmaf(k3.x, qr[28], d3); d3 = fmaf(k3.y, qr[29], d3);
                d3 = fmaf(k3.z, qr[30], d3); d3 = fmaf(k3.w, qr[31], d3);
            }
            float dot = (d0 + d1) + (d2 + d3);
            bool valid = (key >= wlo) && (key <= whi) && (key < S);
            s[j] = valid ? dot : -1e30f;
            cm = fmaxf(cm, s[j]);
        }

        float mn = fmaxf(m, cm);
        float corr = __expf(m - mn);
        l *= corr;
#pragma unroll
        for (int d = 0; d < DH; d++) acc[d] *= corr;
        m = mn;

#pragma unroll
        for (int j = 0; j < 16; j++) {
            float p = (s[j] > -1e29f) ? __expf(s[j] - mn) : 0.0f;
            l += p;
            const float* vrow = &vs[kh * 16 + j][head * DH];
#pragma unroll
            for (int d = 0; d < DH; d += 4) {
                float4 v4 = *(const float4*)&vrow[d];
                acc[d]   = fmaf(p, v4.x, acc[d]);
                acc[d+1] = fmaf(p, v4.y, acc[d+1]);
                acc[d+2] = fmaf(p, v4.z, acc[d+2]);
                acc[d+3] = fmaf(p, v4.w, acc[d+3]);
            }
        }
    }

    float m2 = __shfl_xor_sync(0xffffffffu, m, 16);
    float l2 = __shfl_xor_sync(0xffffffffu, l, 16);
    float mn = fmaxf(m, m2);
    float c1 = __expf(m - mn);
    float c2 = __expf(m2 - mn);
    float lt = l * c1 + l2 * c2;
    float inv = 1.0f / lt;

    float outv[DH];
#pragma unroll
    for (int d = 0; d < DH; d++) {
        float a2 = __shfl_xor_sync(0xffffffffu, acc[d], 16);
        outv[d] = (acc[d] * c1 + a2 * c2) * inv;
    }

    if (kh == 0) {
        float* orow = o + (size_t)i * D + head * DH;
#pragma unroll
        for (int d = 0; d < DH; d += 4) {
            float4 t = {outv[d], outv[d+1], outv[d+2], outv[d+3]};
            *(float4*)&orow[d] = t;
        }
    }
}

// ---------------- launch ----------------
extern "C" void kernel_launch(void* const* d_in, const int* in_sizes, int n_in,
                              void* d_out, int out_size) {
    const float* x  = (const float*)d_in[0];
    const float* wq = (const float*)d_in[1];
    const float* bq = (const float*)d_in[2];
    const float* wk = (const float*)d_in[3];
    const float* bk = (const float*)d_in[4];
    const float* wv = (const float*)d_in[5];
    const float* bv = (const float*)d_in[6];
    const float* wo = (const float*)d_in[7];
    const float* bo = (const float*)d_in[8];
    const float* w1 = (const float*)d_in[9];
    const float* b1 = (const float*)d_in[10];
    const float* w2 = (const float*)d_in[11];
    const float* b2 = (const float*)d_in[12];

    float* h = (float*)d_out;

    float *n, *qkv, *o, *ff;
    cudaGetSymbolAddress((void**)&n,   g_n);
    cudaGetSymbolAddress((void**)&qkv, g_qkv);
    cudaGetSymbolAddress((void**)&o,   g_o);
    cudaGetSymbolAddress((void**)&ff,  g_ff);
    float* q = qkv;
    float* k = qkv + (size_t)S * D;
    float* v = qkv + (size_t)2 * S * D;

    // h = x
    copy_kernel<<<(S * D + 255) / 256, 256>>>(x, h, S * D);

    dim3 grid_d(D / BN, S / BM);        // 4 x 32
    dim3 grid_qkv(D / BN, S / BM, 3);   // fused q,k,v
    dim3 grid_f(FF / BN, S / BM);       // 16 x 32

    for (int l = 0; l < NLAYERS; l++) {
        const float* lwq = wq + (size_t)l * D * D;
        const float* lwk = wk + (size_t)l * D * D;
        const float* lwv = wv + (size_t)l * D * D;
        const float* lwo = wo + (size_t)l * D * D;
        const float* lw1 = w1 + (size_t)l * D * FF;
        const float* lw2 = w2 + (size_t)l * FF * D;
        const float* lbq = bq + (size_t)l * D;
        const float* lbk = bk + (size_t)l * D;
        const float* lbv = bv + (size_t)l * D;
        const float* lbo = bo + (size_t)l * D;
        const float* lb1 = b1 + (size_t)l * FF;
        const float* lb2 = b2 + (size_t)l * D;

        // n = LN(h)
        ln_kernel<<<S / 8, 256>>>(h, n);
        // q,k,v = n @ W + b  (one fused launch)
        qkv_gemm_kernel<<<grid_qkv, 256>>>(n, lwq, lwk, lwv, lbq, lbk, lbv, qkv);
        // o = sliding-window attention
        attn_kernel<<<S / QT, 256>>>(q, k, v, o);
        // h = h + o @ wo + bo
        gemm_kernel<<<grid_d, 256>>>(o, lwo, lbo, h, h, D, D, 0);
        // h = LN(h) (in place)
        ln_kernel<<<S / 8, 256>>>(h, h);
        // ff = gelu(h @ w1 + b1)
        gemm_kernel<<<grid_f, 256>>>(h, lw1, lb1, nullptr, ff, FF, D, 1);
        // h = h + ff @ w2 + b2
        gemm_kernel<<<grid_d, 256>>>(ff, lw2, lb2, h, h, D, FF, 0);
    }
}

// round 11
// speedup vs baseline: 4.3222x; 1.2094x over previous
#include <cuda_runtime.h>
#include <cuda_bf16.h>
#include <math.h>
#include <stdint.h>

// Problem constants
#define S 4096
#define D 256
#define HEADS 8
#define DH 32
#define FF 1024
#define NLAYERS 4
#define HALF_WIN 256
#define EPS 1e-5f
#define QT 16            // queries per attention block

// ---------------- scratch (device globals, no allocation allowed) ----------------
__device__ float g_n  [S * D];
__device__ float g_qkv[3 * S * D];
__device__ float g_o  [S * D];
__device__ float g_ff [S * FF];

// ---------------- helpers ----------------
__device__ __forceinline__ float gelu_tanh(float x) {
    const float c = 0.7978845608028654f; // sqrt(2/pi)
    float x3 = x * x * x;
    float t = tanhf(c * (x + 0.044715f * x3));
    return 0.5f * x * (1.0f + t);
}

__device__ __forceinline__ uint32_t f2tf(float f) {
    uint32_t u;
    asm("cvt.rna.tf32.f32 %0, %1;" : "=r"(u) : "f"(f));
    return u;
}

__device__ __forceinline__ void mma_tf32(float c[4], const uint32_t a[4],
                                         uint32_t b0, uint32_t b1) {
    asm volatile(
        "mma.sync.aligned.m16n8k8.row.col.f32.tf32.tf32.f32 "
        "{%0,%1,%2,%3}, {%4,%5,%6,%7}, {%8,%9}, {%0,%1,%2,%3};\n"
        : "+f"(c[0]), "+f"(c[1]), "+f"(c[2]), "+f"(c[3])
        : "r"(a[0]), "r"(a[1]), "r"(a[2]), "r"(a[3]), "r"(b0), "r"(b1));
}

// ---------------- copy ----------------
__global__ void copy_kernel(const float* __restrict__ in, float* __restrict__ out, int n) {
    int i = blockIdx.x * blockDim.x + threadIdx.x;
    if (i < n) out[i] = in[i];
}

// ---------------- LayerNorm: warp per row, 8 rows per block ----------------
__global__ void ln_kernel(const float* __restrict__ in, float* __restrict__ out) {
    int warp = threadIdx.x >> 5;
    int lane = threadIdx.x & 31;
    int row = blockIdx.x * 8 + warp;
    const float* rp = in + (size_t)row * D + lane * 8;
    float4 v0 = *(const float4*)&rp[0];
    float4 v1 = *(const float4*)&rp[4];
    float s1 = v0.x + v0.y + v0.z + v0.w + v1.x + v1.y + v1.z + v1.w;
    float s2 = v0.x*v0.x + v0.y*v0.y + v0.z*v0.z + v0.w*v0.w
             + v1.x*v1.x + v1.y*v1.y + v1.z*v1.z + v1.w*v1.w;
#pragma unroll
    for (int off = 16; off > 0; off >>= 1) {
        s1 += __shfl_xor_sync(0xffffffffu, s1, off);
        s2 += __shfl_xor_sync(0xffffffffu, s2, off);
    }
    float mean = s1 * (1.0f / D);
    float var  = s2 * (1.0f / D) - mean * mean;
    float rstd = rsqrtf(var + EPS);
    float* op = out + (size_t)row * D + lane * 8;
    float4 o0, o1;
    o0.x = (v0.x - mean) * rstd; o0.y = (v0.y - mean) * rstd;
    o0.z = (v0.z - mean) * rstd; o0.w = (v0.w - mean) * rstd;
    o1.x = (v1.x - mean) * rstd; o1.y = (v1.y - mean) * rstd;
    o1.z = (v1.z - mean) * rstd; o1.w = (v1.w - mean) * rstd;
    *(float4*)&op[0] = o0;
    *(float4*)&op[4] = o1;
}

// ---------------- tf32 tensor-core GEMM: 128x64 tile, BK=16, double-buffered ----------------
#define BM 128
#define BN 64
#define BKT 16
#define AP 20     // As row pitch (u32)
#define BP 72     // Bs row pitch (u32)

__device__ __forceinline__ void gemm_tile_tc(
        const float* __restrict__ A, const float* __restrict__ W,
        const float* __restrict__ bias, const float* __restrict__ res,
        float* __restrict__ C, int N, int K, int act,
        int row0, int col0,
        uint32_t (*As)[BM][AP], uint32_t (*Bs)[BKT][BP]) {
    int tid  = threadIdx.x;
    int warp = tid >> 5;
    int lane = tid & 31;
    int g    = lane >> 2;
    int tig  = lane & 3;
    int wm   = warp & 3;
    int wn   = warp >> 2;

    int ar = tid >> 2;
    int ac = (tid & 3) << 2;
    int br = tid >> 4;
    int bc = (tid & 15) << 2;

    float acc[2][4][4];
#pragma unroll
    for (int mi = 0; mi < 2; mi++)
#pragma unroll
        for (int ni = 0; ni < 4; ni++)
#pragma unroll
            for (int r = 0; r < 4; r++) acc[mi][ni][r] = 0.0f;

    const float* Ar0 = A + (size_t)(row0 + ar) * K;
    const float* Ar1 = A + (size_t)(row0 + ar + 64) * K;

    {
        float4 a0 = *(const float4*)&Ar0[ac];
        float4 a1 = *(const float4*)&Ar1[ac];
        float4 b  = *(const float4*)&W[(size_t)br * N + col0 + bc];
        uint4 ua0 = {f2tf(a0.x), f2tf(a0.y), f2tf(a0.z), f2tf(a0.w)};
        uint4 ua1 = {f2tf(a1.x), f2tf(a1.y), f2tf(a1.z), f2tf(a1.w)};
        uint4 ub  = {f2tf(b.x),  f2tf(b.y),  f2tf(b.z),  f2tf(b.w)};
        *(uint4*)&As[0][ar][ac]      = ua0;
        *(uint4*)&As[0][ar + 64][ac] = ua1;
        *(uint4*)&Bs[0][br][bc]      = ub;
    }
    __syncthreads();

    int nk = K / BKT;
    for (int t = 0; t < nk; t++) {
        int cur = t & 1;
        float4 pa0, pa1, pb;
        if (t + 1 < nk) {
            int kb = (t + 1) * BKT;
            pa0 = *(const float4*)&Ar0[kb + ac];
            pa1 = *(const float4*)&Ar1[kb + ac];
            pb  = *(const float4*)&W[(size_t)(kb + br) * N + col0 + bc];
        }

#pragma unroll
        for (int ks = 0; ks < 2; ks++) {
            uint32_t a[2][4];
#pragma unroll
            for (int mi = 0; mi < 2; mi++) {
                int r = wm * 32 + mi * 16 + g;
                int kbn = ks * 8 + tig;
                a[mi][0] = As[cur][r][kbn];
                a[mi][1] = As[cur][r + 8][kbn];
                a[mi][2] = As[cur][r][kbn + 4];
                a[mi][3] = As[cur][r + 8][kbn + 4];
            }
#pragma unroll
            for (int ni = 0; ni < 4; ni++) {
                int cn = wn * 32 + ni * 8 + g;
                uint32_t b0 = Bs[cur][ks * 8 + tig][cn];
                uint32_t b1 = Bs[cur][ks * 8 + tig + 4][cn];
                mma_tf32(acc[0][ni], a[0], b0, b1);
                mma_tf32(acc[1][ni], a[1], b0, b1);
            }
        }

        if (t + 1 < nk) {
            int nxt = cur ^ 1;
            uint4 ua0 = {f2tf(pa0.x), f2tf(pa0.y), f2tf(pa0.z), f2tf(pa0.w)};
            uint4 ua1 = {f2tf(pa1.x), f2tf(pa1.y), f2tf(pa1.z), f2tf(pa1.w)};
            uint4 ub  = {f2tf(pb.x),  f2tf(pb.y),  f2tf(pb.z),  f2tf(pb.w)};
            *(uint4*)&As[nxt][ar][ac]      = ua0;
            *(uint4*)&As[nxt][ar + 64][ac] = ua1;
            *(uint4*)&Bs[nxt][br][bc]      = ub;
        }
        __syncthreads();
    }

#pragma unroll
    for (int mi = 0; mi < 2; mi++) {
#pragma unroll
        for (int ni = 0; ni < 4; ni++) {
            int r  = row0 + wm * 32 + mi * 16 + g;
            int cc = col0 + wn * 32 + ni * 8 + tig * 2;
            float b0 = __ldg(&bias[cc]);
            float b1 = __ldg(&bias[cc + 1]);
#pragma unroll
            for (int half = 0; half < 2; half++) {
                int rr = r + half * 8;
                float v0 = acc[mi][ni][half * 2 + 0] + b0;
                float v1 = acc[mi][ni][half * 2 + 1] + b1;
                if (act) { v0 = gelu_tanh(v0); v1 = gelu_tanh(v1); }
                if (res) {
                    float2 rv = *(const float2*)&res[(size_t)rr * N + cc];
                    v0 += rv.x; v1 += rv.y;
                }
                float2 ov = {v0, v1};
                *(float2*)&C[(size_t)rr * N + cc] = ov;
            }
        }
    }
}

__global__ void __launch_bounds__(256) gemm_kernel(
        const float* __restrict__ A, const float* __restrict__ W,
        const float* __restrict__ bias, const float* __restrict__ res,
        float* __restrict__ C, int N, int K, int act) {
    __shared__ uint32_t As[2][BM][AP];
    __shared__ uint32_t Bs[2][BKT][BP];
    gemm_tile_tc(A, W, bias, res, C, N, K, act,
                 blockIdx.y * BM, blockIdx.x * BN, As, Bs);
}

__global__ void __launch_bounds__(256) qkv_gemm_kernel(
        const float* __restrict__ A,
        const float* __restrict__ wq, const float* __restrict__ wk,
        const float* __restrict__ wv,
        const float* __restrict__ bq, const float* __restrict__ bk,
        const float* __restrict__ bv,
        float* __restrict__ out /* [3][S*D] */) {
    __shared__ uint32_t As[2][BM][AP];
    __shared__ uint32_t Bs[2][BKT][BP];
    const float* W;
    const float* bias;
    int z = blockIdx.z;
    if (z == 0)      { W = wq; bias = bq; }
    else if (z == 1) { W = wk; bias = bk; }
    else             { W = wv; bias = bv; }
    float* C = out + (size_t)z * S * D;
    gemm_tile_tc(A, W, bias, nullptr, C, D, D, 0,
                 blockIdx.y * BM, blockIdx.x * BN, As, Bs);
}

// ---------------- Sliding-window attention via tf32 mma ----------------
// Block = 16 queries x 8 heads (256 threads, grid = 256). warp = head.
// QK^T: A = Q tile (registers), B = K chunk in natural [key][dim] layout
//       (col-major k x n with k=dim, n=key).
// PV:   computed transposed: O^T = V^T @ P^T, so A = V^T reads vs[key][dim]
//       (natural layout), B = P^T reads ps[q][key] (natural layout).
// Per-lane softmax stats for query rows g and g+8, reduced over the 4-lane
// tig group; rescale factors broadcast via shfl.
#define KS_PITCH 260
#define VS_PITCH 264
#define PS_PITCH 34
#define SMEM_ATTN_BYTES ((32 * KS_PITCH + 32 * VS_PITCH + 8 * 16 * PS_PITCH) * 4)

__global__ void __launch_bounds__(256, 2)
attn_kernel(const float* __restrict__ q, const float* __restrict__ k,
            const float* __restrict__ v, float* __restrict__ o) {
    extern __shared__ uint32_t smem[];
    uint32_t (*ks)[KS_PITCH] = (uint32_t(*)[KS_PITCH])smem;
    uint32_t (*vs)[VS_PITCH] = (uint32_t(*)[VS_PITCH])(smem + 32 * KS_PITCH);

    int warp = threadIdx.x >> 5;   // head
    int lane = threadIdx.x & 31;
    int g    = lane >> 2;          // 0..7
    int tig  = lane & 3;           // 0..3
    uint32_t (*ps)[PS_PITCH] =
        (uint32_t(*)[PS_PITCH])(smem + 32 * KS_PITCH + 32 * VS_PITCH + warp * 16 * PS_PITCH);

    int qb = blockIdx.x * QT;
    const float scale = 0.17677669529663687f; // 1/sqrt(32)

    // Q fragments: aq[kstep][4]; A(m=q, k=dim) row-major
    uint32_t aq[4][4];
#pragma unroll
    for (int kk = 0; kk < 4; kk++) {
        int dcol = warp * 32 + kk * 8 + tig;
        aq[kk][0] = f2tf(q[(size_t)(qb + g)     * D + dcol]     * scale);
        aq[kk][1] = f2tf(q[(size_t)(qb + g + 8) * D + dcol]     * scale);
        aq[kk][2] = f2tf(q[(size_t)(qb + g)     * D + dcol + 4] * scale);
        aq[kk][3] = f2tf(q[(size_t)(qb + g + 8) * D + dcol + 4] * scale);
    }

    int kstart = (max(0, qb - HALF_WIN)) & ~31;
    int kend   = min(S, qb + QT + HALF_WIN);
    kend = (kend + 31) & ~31;

    float m_lo = -1e30f, m_hi = -1e30f;
    float l_lo = 0.0f,   l_hi = 0.0f;
    float acc[2][2][4];   // O^T fragments: [dim-tile][q-tile][4]
#pragma unroll
    for (int a = 0; a < 2; a++)
#pragma unroll
        for (int b = 0; b < 2; b++)
#pragma unroll
            for (int c = 0; c < 4; c++) acc[a][b][c] = 0.0f;

    for (int c0 = kstart; c0 < kend; c0 += 32) {
        __syncthreads();   // previous chunk fully consumed
        // stage K,V rows [c0, c0+32) as tf32
#pragma unroll
        for (int rep = 0; rep < 8; rep++) {
            int idx = threadIdx.x + rep * 256;
            int r  = idx >> 6;
            int c4 = (idx & 63) << 2;
            int grow = c0 + r;
            float4 kf = {0.f, 0.f, 0.f, 0.f};
            float4 vf = {0.f, 0.f, 0.f, 0.f};
            if (grow < S) {
                kf = *(const float4*)&k[(size_t)grow * D + c4];
                vf = *(const float4*)&v[(size_t)grow * D + c4];
            }
            uint4 ku = {f2tf(kf.x), f2tf(kf.y), f2tf(kf.z), f2tf(kf.w)};
            uint4 vu = {f2tf(vf.x), f2tf(vf.y), f2tf(vf.z), f2tf(vf.w)};
            *(uint4*)&ks[r][c4] = ku;
            *(uint4*)&vs[r][c4] = vu;
        }
        __syncthreads();

        // ---- scores S[16 q][32 key] via 16 mma ----
        float sfr[4][4];   // [key-tile][4]; c0=(g,2tig) c1=(g,2tig+1) c2=(g+8,2tig) c3=(g+8,2tig+1)
#pragma unroll
        for (int nt = 0; nt < 4; nt++) {
            sfr[nt][0] = sfr[nt][1] = sfr[nt][2] = sfr[nt][3] = 0.0f;
            const uint32_t* krow = &ks[nt * 8 + g][warp * 32];
#pragma unroll
            for (int kk = 0; kk < 4; kk++) {
                uint32_t b0 = krow[kk * 8 + tig];
                uint32_t b1 = krow[kk * 8 + tig + 4];
                mma_tf32(sfr[nt], aq[kk], b0, b1);
            }
        }

        // ---- mask + chunk max ----
        int qlo = qb + g, qhi = qb + g + 8;
        float cm_lo = -1e30f, cm_hi = -1e30f;
#pragma unroll
        for (int nt = 0; nt < 4; nt++) {
            int k0i = c0 + nt * 8 + tig * 2;
            int k1i = k0i + 1;
            if (k0i < qlo - HALF_WIN || k0i > qlo + HALF_WIN || k0i >= S) sfr[nt][0] = -1e30f;
            if (k1i < qlo - HALF_WIN || k1i > qlo + HALF_WIN || k1i >= S) sfr[nt][1] = -1e30f;
            if (k0i < qhi - HALF_WIN || k0i > qhi + HALF_WIN || k0i >= S) sfr[nt][2] = -1e30f;
            if (k1i < qhi - HALF_WIN || k1i > qhi + HALF_WIN || k1i >= S) sfr[nt][3] = -1e30f;
            cm_lo = fmaxf(cm_lo, fmaxf(sfr[nt][0], sfr[nt][1]));
            cm_hi = fmaxf(cm_hi, fmaxf(sfr[nt][2], sfr[nt][3]));
        }
        cm_lo = fmaxf(cm_lo, __shfl_xor_sync(0xffffffffu, cm_lo, 1));
        cm_lo = fmaxf(cm_lo, __shfl_xor_sync(0xffffffffu, cm_lo, 2));
        cm_hi = fmaxf(cm_hi, __shfl_xor_sync(0xffffffffu, cm_hi, 1));
        cm_hi = fmaxf(cm_hi, __shfl_xor_sync(0xffffffffu, cm_hi, 2));

        float mn_lo = fmaxf(m_lo, cm_lo);
        float mn_hi = fmaxf(m_hi, cm_hi);
        float corr_lo = __expf(m_lo - mn_lo);
        float corr_hi = __expf(m_hi - mn_hi);
        m_lo = mn_lo; m_hi = mn_hi;

        // ---- probabilities -> ps (tf32), plus partial row sums ----
        __syncwarp();      // previous PV reads of ps complete
        float ls_lo = 0.0f, ls_hi = 0.0f;
#pragma unroll
        for (int nt = 0; nt < 4; nt++) {
            float p0 = (sfr[nt][0] > -1e29f) ? __expf(sfr[nt][0] - mn_lo) : 0.0f;
            float p1 = (sfr[nt][1] > -1e29f) ? __expf(sfr[nt][1] - mn_lo) : 0.0f;
            float p2 = (sfr[nt][2] > -1e29f) ? __expf(sfr[nt][2] - mn_hi) : 0.0f;
            float p3 = (sfr[nt][3] > -1e29f) ? __expf(sfr[nt][3] - mn_hi) : 0.0f;
            ls_lo += p0 + p1;
            ls_hi += p2 + p3;
            uint2 plo = {f2tf(p0), f2tf(p1)};
            uint2 phi = {f2tf(p2), f2tf(p3)};
            *(uint2*)&ps[g][nt * 8 + tig * 2]     = plo;
            *(uint2*)&ps[g + 8][nt * 8 + tig * 2] = phi;
        }
        __syncwarp();      // ps visible to all lanes

        ls_lo += __shfl_xor_sync(0xffffffffu, ls_lo, 1);
        ls_lo += __shfl_xor_sync(0xffffffffu, ls_lo, 2);
        ls_hi += __shfl_xor_sync(0xffffffffu, ls_hi, 1);
        ls_hi += __shfl_xor_sync(0xffffffffu, ls_hi, 2);
        l_lo = l_lo * corr_lo + ls_lo;
        l_hi = l_hi * corr_hi + ls_hi;

        // ---- rescale O^T accumulators: need corr per query column ----
        // query qq<8 held as corr_lo by lanes g==qq (src lane qq*4); qq>=8 as corr_hi
        float cq0 = __shfl_sync(0xffffffffu, corr_lo, tig * 8);       // q = 2tig
        float cq1 = __shfl_sync(0xffffffffu, corr_lo, tig * 8 + 4);   // q = 2tig+1
        float cq2 = __shfl_sync(0xffffffffu, corr_hi, tig * 8);       // q = 2tig+8
        float cq3 = __shfl_sync(0xffffffffu, corr_hi, tig * 8 + 4);   // q = 2tig+9
#pragma unroll
        for (int mt = 0; mt < 2; mt++) {
            acc[mt][0][0] *= cq0; acc[mt][0][1] *= cq1;
            acc[mt][0][2] *= cq0; acc[mt][0][3] *= cq1;
            acc[mt][1][0] *= cq2; acc[mt][1][1] *= cq3;
            acc[mt][1][2] *= cq2; acc[mt][1][3] *= cq3;
        }

        // ---- PV: O^T += V^T @ P^T (16 mma) ----
#pragma unroll
        for (int kk = 0; kk < 4; kk++) {
            uint32_t b0A = ps[g][kk * 8 + tig];
            uint32_t b1A = ps[g][kk * 8 + tig + 4];
            uint32_t b0B = ps[8 + g][kk * 8 + tig];
            uint32_t b1B = ps[8 + g][kk * 8 + tig + 4];
#pragma unroll
            for (int mt = 0; mt < 2; mt++) {
                const uint32_t* v0 = &vs[kk * 8 + tig][warp * 32 + mt * 16];
                const uint32_t* v4 = &vs[kk * 8 + tig + 4][warp * 32 + mt * 16];
                uint32_t a[4] = { v0[g], v0[g + 8], v4[g], v4[g + 8] };
                mma_tf32(acc[mt][0], a, b0A, b1A);
                mma_tf32(acc[mt][1], a, b0B, b1B);
            }
        }
    }

    // ---- epilogue: divide by l (per query column), write O ----
    float lq0 = __shfl_sync(0xffffffffu, l_lo, tig * 8);
    float lq1 = __shfl_sync(0xffffffffu, l_lo, tig * 8 + 4);
    float lq2 = __shfl_sync(0xffffffffu, l_hi, tig * 8);
    float lq3 = __shfl_sync(0xffffffffu, l_hi, tig * 8 + 4);
    float i0 = 1.0f / lq0, i1 = 1.0f / lq1, i2 = 1.0f / lq2, i3 = 1.0f / lq3;
    int qA = qb + tig * 2, qB = qA + 1, qC = qA + 8, qD = qB + 8;
#pragma unroll
    for (int mt = 0; mt < 2; mt++) {
        int d0 = warp * 32 + mt * 16 + g;
        int d1 = d0 + 8;
        o[(size_t)qA * D + d0] = acc[mt][0][0] * i0;
        o[(size_t)qB * D + d0] = acc[mt][0][1] * i1;
        o[(size_t)qA * D + d1] = acc[mt][0][2] * i0;
        o[(size_t)qB * D + d1] = acc[mt][0][3] * i1;
        o[(size_t)qC * D + d0] = acc[mt][1][0] * i2;
        o[(size_t)qD * D + d0] = acc[mt][1][1] * i3;
        o[(size_t)qC * D + d1] = acc[mt][1][2] * i2;
        o[(size_t)qD * D + d1] = acc[mt][1][3] * i3;
    }
}

// ---------------- launch ----------------
extern "C" void kernel_launch(void* const* d_in, const int* in_sizes, int n_in,
                              void* d_out, int out_size) {
    const float* x  = (const float*)d_in[0];
    const float* wq = (const float*)d_in[1];
    const float* bq = (const float*)d_in[2];
    const float* wk = (const float*)d_in[3];
    const float* bk = (const float*)d_in[4];
    const float* wv = (const float*)d_in[5];
    const float* bv = (const float*)d_in[6];
    const float* wo = (const float*)d_in[7];
    const float* bo = (const float*)d_in[8];
    const float* w1 = (const float*)d_in[9];
    const float* b1 = (const float*)d_in[10];
    const float* w2 = (const float*)d_in[11];
    const float* b2 = (const float*)d_in[12];

    float* h = (float*)d_out;

    float *n, *qkv, *o, *ff;
    cudaGetSymbolAddress((void**)&n,   g_n);
    cudaGetSymbolAddress((void**)&qkv, g_qkv);
    cudaGetSymbolAddress((void**)&o,   g_o);
    cudaGetSymbolAddress((void**)&ff,  g_ff);
    float* q = qkv;
    float* k = qkv + (size_t)S * D;
    float* v = qkv + (size_t)2 * S * D;

    // opt in to >48KB dynamic smem for the attention kernel (idempotent)
    cudaFuncSetAttribute(attn_kernel, cudaFuncAttributeMaxDynamicSharedMemorySize,
                         SMEM_ATTN_BYTES);

    // h = x
    copy_kernel<<<(S * D + 255) / 256, 256>>>(x, h, S * D);

    dim3 grid_d(D / BN, S / BM);        // 4 x 32
    dim3 grid_qkv(D / BN, S / BM, 3);   // fused q,k,v
    dim3 grid_f(FF / BN, S / BM);       // 16 x 32

    for (int l = 0; l < NLAYERS; l++) {
        const float* lwq = wq + (size_t)l * D * D;
        const float* lwk = wk + (size_t)l * D * D;
        const float* lwv = wv + (size_t)l * D * D;
        const float* lwo = wo + (size_t)l * D * D;
        const float* lw1 = w1 + (size_t)l * D * FF;
        const float* lw2 = w2 + (size_t)l * FF * D;
        const float* lbq = bq + (size_t)l * D;
        const float* lbk = bk + (size_t)l * D;
        const float* lbv = bv + (size_t)l * D;
        const float* lbo = bo + (size_t)l * D;
        const float* lb1 = b1 + (size_t)l * FF;
        const float* lb2 = b2 + (size_t)l * D;

        // n = LN(h)
        ln_kernel<<<S / 8, 256>>>(h, n);
        // q,k,v = n @ W + b  (one fused launch)
        qkv_gemm_kernel<<<grid_qkv, 256>>>(n, lwq, lwk, lwv, lbq, lbk, lbv, qkv);
        // o = sliding-window attention (tf32 mma)
        attn_kernel<<<S / QT, 256, SMEM_ATTN_BYTES>>>(q, k, v, o);
        // h = h + o @ wo + bo
        gemm_kernel<<<grid_d, 256>>>(o, lwo, lbo, h, h, D, D, 0);
        // h = LN(h) (in place)
        ln_kernel<<<S / 8, 256>>>(h, h);
        // ff = gelu(h @ w1 + b1)
        gemm_kernel<<<grid_f, 256>>>(h, lw1, lb1, nullptr, ff, FF, D, 1);
        // h = h + ff @ w2 + b2
        gemm_kernel<<<grid_d, 256>>>(ff, lw2, lb2, h, h, D, FF, 0);
    }
}

// round 13
// speedup vs baseline: 5.1281x; 1.1865x over previous
#include <cuda_runtime.h>
#include <cuda_bf16.h>
#include <math.h>
#include <stdint.h>

// Problem constants
#define S 4096
#define D 256
#define HEADS 8
#define DH 32
#define FF 1024
#define NLAYERS 4
#define HALF_WIN 256
#define EPS 1e-5f
#define QT 16            // queries per attention block

// ---------------- scratch (device globals, no allocation allowed) ----------------
__device__ float g_n  [S * D];
__device__ float g_qkv[3 * S * D];
__device__ float g_o  [S * D];
__device__ float g_ff [S * FF];

// ---------------- helpers ----------------
__device__ __forceinline__ float gelu_tanh(float x) {
    const float c = 0.7978845608028654f; // sqrt(2/pi)
    float x3 = x * x * x;
    float t = tanhf(c * (x + 0.044715f * x3));
    return 0.5f * x * (1.0f + t);
}

__device__ __forceinline__ uint32_t f2tf(float f) {
    uint32_t u;
    asm("cvt.rna.tf32.f32 %0, %1;" : "=r"(u) : "f"(f));
    return u;
}

__device__ __forceinline__ void mma_tf32(float c[4], const uint32_t a[4],
                                         uint32_t b0, uint32_t b1) {
    asm volatile(
        "mma.sync.aligned.m16n8k8.row.col.f32.tf32.tf32.f32 "
        "{%0,%1,%2,%3}, {%4,%5,%6,%7}, {%8,%9}, {%0,%1,%2,%3};\n"
        : "+f"(c[0]), "+f"(c[1]), "+f"(c[2]), "+f"(c[3])
        : "r"(a[0]), "r"(a[1]), "r"(a[2]), "r"(a[3]), "r"(b0), "r"(b1));
}

// ---------------- copy ----------------
__global__ void copy_kernel(const float* __restrict__ in, float* __restrict__ out, int n) {
    int i = blockIdx.x * blockDim.x + threadIdx.x;
    if (i < n) out[i] = in[i];
}

// ---------------- LayerNorm: warp per row, 8 rows per block ----------------
__global__ void ln_kernel(const float* __restrict__ in, float* __restrict__ out) {
    int warp = threadIdx.x >> 5;
    int lane = threadIdx.x & 31;
    int row = blockIdx.x * 8 + warp;
    const float* rp = in + (size_t)row * D + lane * 8;
    float4 v0 = *(const float4*)&rp[0];
    float4 v1 = *(const float4*)&rp[4];
    float s1 = v0.x + v0.y + v0.z + v0.w + v1.x + v1.y + v1.z + v1.w;
    float s2 = v0.x*v0.x + v0.y*v0.y + v0.z*v0.z + v0.w*v0.w
             + v1.x*v1.x + v1.y*v1.y + v1.z*v1.z + v1.w*v1.w;
#pragma unroll
    for (int off = 16; off > 0; off >>= 1) {
        s1 += __shfl_xor_sync(0xffffffffu, s1, off);
        s2 += __shfl_xor_sync(0xffffffffu, s2, off);
    }
    float mean = s1 * (1.0f / D);
    float var  = s2 * (1.0f / D) - mean * mean;
    float rstd = rsqrtf(var + EPS);
    float* op = out + (size_t)row * D + lane * 8;
    float4 o0, o1;
    o0.x = (v0.x - mean) * rstd; o0.y = (v0.y - mean) * rstd;
    o0.z = (v0.z - mean) * rstd; o0.w = (v0.w - mean) * rstd;
    o1.x = (v1.x - mean) * rstd; o1.y = (v1.y - mean) * rstd;
    o1.z = (v1.z - mean) * rstd; o1.w = (v1.w - mean) * rstd;
    *(float4*)&op[0] = o0;
    *(float4*)&op[4] = o1;
}

// ---------------- tf32 tensor-core GEMM, templated on M-tile (MI*64) ----------------
#define BN 64
#define BKT 16
#define AP 20     // As row pitch (u32)
#define BP 72     // Bs row pitch (u32)

template<int MI>
__device__ __forceinline__ void gemm_tile_tc(
        const float* __restrict__ A, const float* __restrict__ W,
        const float* __restrict__ bias, const float* __restrict__ res,
        float* __restrict__ C, int N, int K, int act,
        int row0, int col0,
        uint32_t (*As)[MI * 64][AP], uint32_t (*Bs)[BKT][BP]) {
    int tid  = threadIdx.x;
    int warp = tid >> 5;
    int lane = tid & 31;
    int g    = lane >> 2;
    int tig  = lane & 3;
    int wm   = warp & 3;
    int wn   = warp >> 2;

    int ar = tid >> 2;            // 0..63
    int ac = (tid & 3) << 2;
    int br = tid >> 4;
    int bc = (tid & 15) << 2;

    float acc[MI][4][4];
#pragma unroll
    for (int mi = 0; mi < MI; mi++)
#pragma unroll
        for (int ni = 0; ni < 4; ni++)
#pragma unroll
            for (int r = 0; r < 4; r++) acc[mi][ni][r] = 0.0f;

    const float* Ar0 = A + (size_t)(row0 + ar) * K;
    const float* Ar1 = (MI == 2) ? A + (size_t)(row0 + ar + 64) * K : Ar0;

    {
        float4 a0 = *(const float4*)&Ar0[ac];
        uint4 ua0 = {f2tf(a0.x), f2tf(a0.y), f2tf(a0.z), f2tf(a0.w)};
        *(uint4*)&As[0][ar][ac] = ua0;
        if (MI == 2) {
            float4 a1 = *(const float4*)&Ar1[ac];
            uint4 ua1 = {f2tf(a1.x), f2tf(a1.y), f2tf(a1.z), f2tf(a1.w)};
            *(uint4*)&As[0][ar + 64][ac] = ua1;
        }
        float4 b = *(const float4*)&W[(size_t)br * N + col0 + bc];
        uint4 ub = {f2tf(b.x), f2tf(b.y), f2tf(b.z), f2tf(b.w)};
        *(uint4*)&Bs[0][br][bc] = ub;
    }
    __syncthreads();

    int nk = K / BKT;
    for (int t = 0; t < nk; t++) {
        int cur = t & 1;
        float4 pa0, pa1, pb;
        if (t + 1 < nk) {
            int kb = (t + 1) * BKT;
            pa0 = *(const float4*)&Ar0[kb + ac];
            if (MI == 2) pa1 = *(const float4*)&Ar1[kb + ac];
            pb  = *(const float4*)&W[(size_t)(kb + br) * N + col0 + bc];
        }

#pragma unroll
        for (int ks = 0; ks < 2; ks++) {
            uint32_t a[MI][4];
#pragma unroll
            for (int mi = 0; mi < MI; mi++) {
                int r = wm * (16 * MI) + mi * 16 + g;
                int kbn = ks * 8 + tig;
                a[mi][0] = As[cur][r][kbn];
                a[mi][1] = As[cur][r + 8][kbn];
                a[mi][2] = As[cur][r][kbn + 4];
                a[mi][3] = As[cur][r + 8][kbn + 4];
            }
#pragma unroll
            for (int ni = 0; ni < 4; ni++) {
                int cn = wn * 32 + ni * 8 + g;
                uint32_t b0 = Bs[cur][ks * 8 + tig][cn];
                uint32_t b1 = Bs[cur][ks * 8 + tig + 4][cn];
#pragma unroll
                for (int mi = 0; mi < MI; mi++)
                    mma_tf32(acc[mi][ni], a[mi], b0, b1);
            }
        }

        if (t + 1 < nk) {
            int nxt = cur ^ 1;
            uint4 ua0 = {f2tf(pa0.x), f2tf(pa0.y), f2tf(pa0.z), f2tf(pa0.w)};
            *(uint4*)&As[nxt][ar][ac] = ua0;
            if (MI == 2) {
                uint4 ua1 = {f2tf(pa1.x), f2tf(pa1.y), f2tf(pa1.z), f2tf(pa1.w)};
                *(uint4*)&As[nxt][ar + 64][ac] = ua1;
            }
            uint4 ub = {f2tf(pb.x), f2tf(pb.y), f2tf(pb.z), f2tf(pb.w)};
            *(uint4*)&Bs[nxt][br][bc] = ub;
        }
        __syncthreads();
    }

#pragma unroll
    for (int mi = 0; mi < MI; mi++) {
#pragma unroll
        for (int ni = 0; ni < 4; ni++) {
            int r  = row0 + wm * (16 * MI) + mi * 16 + g;
            int cc = col0 + wn * 32 + ni * 8 + tig * 2;
            float b0 = __ldg(&bias[cc]);
            float b1 = __ldg(&bias[cc + 1]);
#pragma unroll
            for (int half = 0; half < 2; half++) {
                int rr = r + half * 8;
                float v0 = acc[mi][ni][half * 2 + 0] + b0;
                float v1 = acc[mi][ni][half * 2 + 1] + b1;
                if (act) { v0 = gelu_tanh(v0); v1 = gelu_tanh(v1); }
                if (res) {
                    float2 rv = *(const float2*)&res[(size_t)rr * N + cc];
                    v0 += rv.x; v1 += rv.y;
                }
                float2 ov = {v0, v1};
                *(float2*)&C[(size_t)rr * N + cc] = ov;
            }
        }
    }
}

template<int MI>
__global__ void __launch_bounds__(256) gemm_kernel_t(
        const float* __restrict__ A, const float* __restrict__ W,
        const float* __restrict__ bias, const float* __restrict__ res,
        float* __restrict__ C, int N, int K, int act) {
    __shared__ uint32_t As[2][MI * 64][AP];
    __shared__ uint32_t Bs[2][BKT][BP];
    gemm_tile_tc<MI>(A, W, bias, res, C, N, K, act,
                     blockIdx.y * (MI * 64), blockIdx.x * BN, As, Bs);
}

__global__ void __launch_bounds__(256) qkv_gemm_kernel(
        const float* __restrict__ A,
        const float* __restrict__ wq, const float* __restrict__ wk,
        const float* __restrict__ wv,
        const float* __restrict__ bq, const float* __restrict__ bk,
        const float* __restrict__ bv,
        float* __restrict__ out /* [3][S*D] */) {
    __shared__ uint32_t As[2][128][AP];
    __shared__ uint32_t Bs[2][BKT][BP];
    const float* W;
    const float* bias;
    int z = blockIdx.z;
    if (z == 0)      { W = wq; bias = bq; }
    else if (z == 1) { W = wk; bias = bk; }
    else             { W = wv; bias = bv; }
    float* C = out + (size_t)z * S * D;
    gemm_tile_tc<2>(A, W, bias, nullptr, C, D, D, 0,
                    blockIdx.y * 128, blockIdx.x * BN, As, Bs);
}

// ---------------- Sliding-window attention via tf32 mma ----------------
// Block = 16 queries x 8 heads (256 threads, grid = 256). warp = head.
// Clean/masked chunk split: only window-edge chunks pay masking ALU.
// P^T fragments for the PV mma are produced by an in-warp shuffle transpose
// (4-lane groups) instead of an SMEM round trip.
#define KS_PITCH 260
#define VS_PITCH 264
#define SMEM_ATTN_BYTES ((32 * KS_PITCH + 32 * VS_PITCH) * 4)

__global__ void __launch_bounds__(256, 2)
attn_kernel(const float* __restrict__ q, const float* __restrict__ k,
            const float* __restrict__ v, float* __restrict__ o) {
    extern __shared__ uint32_t smem[];
    uint32_t (*ks)[KS_PITCH] = (uint32_t(*)[KS_PITCH])smem;
    uint32_t (*vs)[VS_PITCH] = (uint32_t(*)[VS_PITCH])(smem + 32 * KS_PITCH);

    int warp = threadIdx.x >> 5;   // head
    int lane = threadIdx.x & 31;
    int g    = lane >> 2;          // 0..7
    int tig  = lane & 3;           // 0..3

    int qb = blockIdx.x * QT;
    const float scale = 0.17677669529663687f; // 1/sqrt(32)

    // Q fragments: aq[kstep][4]
    uint32_t aq[4][4];
#pragma unroll
    for (int kk = 0; kk < 4; kk++) {
        int dcol = warp * 32 + kk * 8 + tig;
        aq[kk][0] = f2tf(q[(size_t)(qb + g)     * D + dcol]     * scale);
        aq[kk][1] = f2tf(q[(size_t)(qb + g + 8) * D + dcol]     * scale);
        aq[kk][2] = f2tf(q[(size_t)(qb + g)     * D + dcol + 4] * scale);
        aq[kk][3] = f2tf(q[(size_t)(qb + g + 8) * D + dcol + 4] * scale);
    }

    int kstart = (max(0, qb - HALF_WIN)) & ~31;
    int kend   = min(S, qb + QT + HALF_WIN);
    kend = (kend + 31) & ~31;

    float m_lo = -1e30f, m_hi = -1e30f;
    float l_lo = 0.0f,   l_hi = 0.0f;
    float acc[2][2][4];   // O^T fragments: [dim-tile][q-tile][4]
#pragma unroll
    for (int a = 0; a < 2; a++)
#pragma unroll
        for (int b = 0; b < 2; b++)
#pragma unroll
            for (int c = 0; c < 4; c++) acc[a][b][c] = 0.0f;

    for (int c0 = kstart; c0 < kend; c0 += 32) {
        __syncthreads();   // previous chunk fully consumed
        // stage K,V rows [c0, c0+32) as tf32
#pragma unroll
        for (int rep = 0; rep < 8; rep++) {
            int idx = threadIdx.x + rep * 256;
            int r  = idx >> 6;
            int c4 = (idx & 63) << 2;
            int grow = c0 + r;
            float4 kf = {0.f, 0.f, 0.f, 0.f};
            float4 vf = {0.f, 0.f, 0.f, 0.f};
            if (grow < S) {
                kf = *(const float4*)&k[(size_t)grow * D + c4];
                vf = *(const float4*)&v[(size_t)grow * D + c4];
            }
            uint4 ku = {f2tf(kf.x), f2tf(kf.y), f2tf(kf.z), f2tf(kf.w)};
            uint4 vu = {f2tf(vf.x), f2tf(vf.y), f2tf(vf.z), f2tf(vf.w)};
            *(uint4*)&ks[r][c4] = ku;
            *(uint4*)&vs[r][c4] = vu;
        }
        __syncthreads();

        // ---- scores S[16 q][32 key] via 16 mma ----
        float sfr[4][4];
#pragma unroll
        for (int nt = 0; nt < 4; nt++) {
            sfr[nt][0] = sfr[nt][1] = sfr[nt][2] = sfr[nt][3] = 0.0f;
            const uint32_t* krow = &ks[nt * 8 + g][warp * 32];
#pragma unroll
            for (int kk = 0; kk < 4; kk++) {
                uint32_t b0 = krow[kk * 8 + tig];
                uint32_t b1 = krow[kk * 8 + tig + 4];
                mma_tf32(sfr[nt], aq[kk], b0, b1);
            }
        }

        bool maskedChunk = (c0 < qb + QT - 1 - HALF_WIN) ||
                           (c0 + 31 > qb + HALF_WIN) ||
                           (c0 + 31 >= S);

        float cm_lo = -1e30f, cm_hi = -1e30f;
        if (maskedChunk) {
            int qlo = qb + g, qhi = qb + g + 8;
#pragma unroll
            for (int nt = 0; nt < 4; nt++) {
                int k0i = c0 + nt * 8 + tig * 2;
                int k1i = k0i + 1;
                if (k0i < qlo - HALF_WIN || k0i > qlo + HALF_WIN || k0i >= S) sfr[nt][0] = -1e30f;
                if (k1i < qlo - HALF_WIN || k1i > qlo + HALF_WIN || k1i >= S) sfr[nt][1] = -1e30f;
                if (k0i < qhi - HALF_WIN || k0i > qhi + HALF_WIN || k0i >= S) sfr[nt][2] = -1e30f;
                if (k1i < qhi - HALF_WIN || k1i > qhi + HALF_WIN || k1i >= S) sfr[nt][3] = -1e30f;
                cm_lo = fmaxf(cm_lo, fmaxf(sfr[nt][0], sfr[nt][1]));
                cm_hi = fmaxf(cm_hi, fmaxf(sfr[nt][2], sfr[nt][3]));
            }
        } else {
#pragma unroll
            for (int nt = 0; nt < 4; nt++) {
                cm_lo = fmaxf(cm_lo, fmaxf(sfr[nt][0], sfr[nt][1]));
                cm_hi = fmaxf(cm_hi, fmaxf(sfr[nt][2], sfr[nt][3]));
            }
        }
        cm_lo = fmaxf(cm_lo, __shfl_xor_sync(0xffffffffu, cm_lo, 1));
        cm_lo = fmaxf(cm_lo, __shfl_xor_sync(0xffffffffu, cm_lo, 2));
        cm_hi = fmaxf(cm_hi, __shfl_xor_sync(0xffffffffu, cm_hi, 1));
        cm_hi = fmaxf(cm_hi, __shfl_xor_sync(0xffffffffu, cm_hi, 2));

        float mn_lo = fmaxf(m_lo, cm_lo);
        float mn_hi = fmaxf(m_hi, cm_hi);
        float corr_lo = __expf(m_lo - mn_lo);
        float corr_hi = __expf(m_hi - mn_hi);
        m_lo = mn_lo; m_hi = mn_hi;

        // ---- probabilities in registers (overwrite sfr) + partial row sums ----
        float ls_lo = 0.0f, ls_hi = 0.0f;
        if (maskedChunk) {
#pragma unroll
            for (int nt = 0; nt < 4; nt++) {
                float p0 = (sfr[nt][0] > -1e29f) ? __expf(sfr[nt][0] - mn_lo) : 0.0f;
                float p1 = (sfr[nt][1] > -1e29f) ? __expf(sfr[nt][1] - mn_lo) : 0.0f;
                float p2 = (sfr[nt][2] > -1e29f) ? __expf(sfr[nt][2] - mn_hi) : 0.0f;
                float p3 = (sfr[nt][3] > -1e29f) ? __expf(sfr[nt][3] - mn_hi) : 0.0f;
                ls_lo += p0 + p1; ls_hi += p2 + p3;
                sfr[nt][0] = p0; sfr[nt][1] = p1; sfr[nt][2] = p2; sfr[nt][3] = p3;
            }
        } else {
#pragma unroll
            for (int nt = 0; nt < 4; nt++) {
                float p0 = __expf(sfr[nt][0] - mn_lo);
                float p1 = __expf(sfr[nt][1] - mn_lo);
                float p2 = __expf(sfr[nt][2] - mn_hi);
                float p3 = __expf(sfr[nt][3] - mn_hi);
                ls_lo += p0 + p1; ls_hi += p2 + p3;
                sfr[nt][0] = p0; sfr[nt][1] = p1; sfr[nt][2] = p2; sfr[nt][3] = p3;
            }
        }

        ls_lo += __shfl_xor_sync(0xffffffffu, ls_lo, 1);
        ls_lo += __shfl_xor_sync(0xffffffffu, ls_lo, 2);
        ls_hi += __shfl_xor_sync(0xffffffffu, ls_hi, 1);
        ls_hi += __shfl_xor_sync(0xffffffffu, ls_hi, 2);
        l_lo = l_lo * corr_lo + ls_lo;
        l_hi = l_hi * corr_hi + ls_hi;

        // ---- rescale O^T accumulators (corr per query column) ----
        float cq0 = __shfl_sync(0xffffffffu, corr_lo, tig * 8);
        float cq1 = __shfl_sync(0xffffffffu, corr_lo, tig * 8 + 4);
        float cq2 = __shfl_sync(0xffffffffu, corr_hi, tig * 8);
        float cq3 = __shfl_sync(0xffffffffu, corr_hi, tig * 8 + 4);
#pragma unroll
        for (int mt = 0; mt < 2; mt++) {
            acc[mt][0][0] *= cq0; acc[mt][0][1] *= cq1;
            acc[mt][0][2] *= cq0; acc[mt][0][3] *= cq1;
            acc[mt][1][0] *= cq2; acc[mt][1][1] *= cq3;
            acc[mt][1][2] *= cq2; acc[mt][1][3] *= cq3;
        }

        // ---- PV: O^T += V^T @ P^T; P^T B-frags via shuffle transpose ----
        int L0 = g * 4 + (tig >> 1);
        int L1 = L0 + 2;
        bool odd = (tig & 1);
#pragma unroll
        for (int kk = 0; kk < 4; kk++) {
            float t00 = __shfl_sync(0xffffffffu, sfr[kk][0], L0);
            float t01 = __shfl_sync(0xffffffffu, sfr[kk][1], L0);
            float t02 = __shfl_sync(0xffffffffu, sfr[kk][2], L0);
            float t03 = __shfl_sync(0xffffffffu, sfr[kk][3], L0);
            float t10 = __shfl_sync(0xffffffffu, sfr[kk][0], L1);
            float t11 = __shfl_sync(0xffffffffu, sfr[kk][1], L1);
            float t12 = __shfl_sync(0xffffffffu, sfr[kk][2], L1);
            float t13 = __shfl_sync(0xffffffffu, sfr[kk][3], L1);
            uint32_t b0A = f2tf(odd ? t01 : t00);
            uint32_t b0B = f2tf(odd ? t03 : t02);
            uint32_t b1A = f2tf(odd ? t11 : t10);
            uint32_t b1B = f2tf(odd ? t13 : t12);
#pragma unroll
            for (int mt = 0; mt < 2; mt++) {
                const uint32_t* v0 = &vs[kk * 8 + tig][warp * 32 + mt * 16];
                const uint32_t* v4 = &vs[kk * 8 + tig + 4][warp * 32 + mt * 16];
                uint32_t a[4] = { v0[g], v0[g + 8], v4[g], v4[g + 8] };
                mma_tf32(acc[mt][0], a, b0A, b1A);
                mma_tf32(acc[mt][1], a, b0B, b1B);
            }
        }
    }

    // ---- epilogue: divide by l (per query column), write O ----
    float lq0 = __shfl_sync(0xffffffffu, l_lo, tig * 8);
    float lq1 = __shfl_sync(0xffffffffu, l_lo, tig * 8 + 4);
    float lq2 = __shfl_sync(0xffffffffu, l_hi, tig * 8);
    float lq3 = __shfl_sync(0xffffffffu, l_hi, tig * 8 + 4);
    float i0 = 1.0f / lq0, i1 = 1.0f / lq1, i2 = 1.0f / lq2, i3 = 1.0f / lq3;
    int qA = qb + tig * 2, qB = qA + 1, qC = qA + 8, qD = qB + 8;
#pragma unroll
    for (int mt = 0; mt < 2; mt++) {
        int d0 = warp * 32 + mt * 16 + g;
        int d1 = d0 + 8;
        o[(size_t)qA * D + d0] = acc[mt][0][0] * i0;
        o[(size_t)qB * D + d0] = acc[mt][0][1] * i1;
        o[(size_t)qA * D + d1] = acc[mt][0][2] * i0;
        o[(size_t)qB * D + d1] = acc[mt][0][3] * i1;
        o[(size_t)qC * D + d0] = acc[mt][1][0] * i2;
        o[(size_t)qD * D + d0] = acc[mt][1][1] * i3;
        o[(size_t)qC * D + d1] = acc[mt][1][2] * i2;
        o[(size_t)qD * D + d1] = acc[mt][1][3] * i3;
    }
}

// ---------------- launch ----------------
extern "C" void kernel_launch(void* const* d_in, const int* in_sizes, int n_in,
                              void* d_out, int out_size) {
    const float* x  = (const float*)d_in[0];
    const float* wq = (const float*)d_in[1];
    const float* bq = (const float*)d_in[2];
    const float* wk = (const float*)d_in[3];
    const float* bk = (const float*)d_in[4];
    const float* wv = (const float*)d_in[5];
    const float* bv = (const float*)d_in[6];
    const float* wo = (const float*)d_in[7];
    const float* bo = (const float*)d_in[8];
    const float* w1 = (const float*)d_in[9];
    const float* b1 = (const float*)d_in[10];
    const float* w2 = (const float*)d_in[11];
    const float* b2 = (const float*)d_in[12];

    float* h = (float*)d_out;

    float *n, *qkv, *o, *ff;
    cudaGetSymbolAddress((void**)&n,   g_n);
    cudaGetSymbolAddress((void**)&qkv, g_qkv);
    cudaGetSymbolAddress((void**)&o,   g_o);
    cudaGetSymbolAddress((void**)&ff,  g_ff);
    float* q = qkv;
    float* k = qkv + (size_t)S * D;
    float* v = qkv + (size_t)2 * S * D;

    // opt in to >48KB dynamic smem for the attention kernel (idempotent)
    cudaFuncSetAttribute(attn_kernel, cudaFuncAttributeMaxDynamicSharedMemorySize,
                         SMEM_ATTN_BYTES);

    // h = x
    copy_kernel<<<(S * D + 255) / 256, 256>>>(x, h, S * D);

    dim3 grid_qkv(D / BN, S / 128, 3);   // 4 x 32 x 3
    dim3 grid_d64(D / BN, S / 64);       // 4 x 64 = 256 blocks (BM=64)
    dim3 grid_f(FF / BN, S / 128);       // 16 x 32

    for (int l = 0; l < NLAYERS; l++) {
        const float* lwq = wq + (size_t)l * D * D;
        const float* lwk = wk + (size_t)l * D * D;
        const float* lwv = wv + (size_t)l * D * D;
        const float* lwo = wo + (size_t)l * D * D;
        const float* lw1 = w1 + (size_t)l * D * FF;
        const float* lw2 = w2 + (size_t)l * FF * D;
        const float* lbq = bq + (size_t)l * D;
        const float* lbk = bk + (size_t)l * D;
        const float* lbv = bv + (size_t)l * D;
        const float* lbo = bo + (size_t)l * D;
        const float* lb1 = b1 + (size_t)l * FF;
        const float* lb2 = b2 + (size_t)l * D;

        // n = LN(h)
        ln_kernel<<<S / 8, 256>>>(h, n);
        // q,k,v = n @ W + b  (one fused launch)
        qkv_gemm_kernel<<<grid_qkv, 256>>>(n, lwq, lwk, lwv, lbq, lbk, lbv, qkv);
        // o = sliding-window attention (tf32 mma)
        attn_kernel<<<S / QT, 256, SMEM_ATTN_BYTES>>>(q, k, v, o);
        // h = h + o @ wo + bo   (BM=64 -> 256 blocks)
        gemm_kernel_t<1><<<grid_d64, 256>>>(o, lwo, lbo, h, h, D, D, 0);
        // h = LN(h) (in place)
        ln_kernel<<<S / 8, 256>>>(h, h);
        // ff = gelu(h @ w1 + b1)
        gemm_kernel_t<2><<<grid_f, 256>>>(h, lw1, lb1, nullptr, ff, FF, D, 1);
        // h = h + ff @ w2 + b2  (BM=64 -> 256 blocks)
        gemm_kernel_t<1><<<grid_d64, 256>>>(ff, lw2, lb2, h, h, D, FF, 0);
    }
}